// round 4
// baseline (speedup 1.0000x reference)
#include <cuda_runtime.h>

// NonLocalLoss: B=4, C=64, N=64*64=4096, two branches (student/teacher) sharing weights.
// out[b,c] = mean_n x + (fsg_w @ q)/N + fsg_b ; q[c] = sum_n g[c,n]*rowsum[n]
// rowsum[n] = sum_m softmax_flat(F)[n,m], F = s^T f. Flash-style single pass over F.

#define N_SP 4096
#define N_C  64
#define N_BB 8   // (branch*4 + batch)

// Scratch (device globals are the allowed scratch mechanism)
__device__ float g_s[(size_t)N_BB * N_C * N_SP];   // s in [C][N] layout per bb
__device__ float g_f[(size_t)N_BB * N_C * N_SP];   // f in [C][N]
__device__ float g_g[(size_t)N_BB * N_C * N_SP];   // g in [C][N]
__device__ float g_rowM[N_BB * N_SP];
__device__ float g_rowE[N_BB * N_SP];
__device__ float g_q[N_BB * N_C];
__device__ float g_sumx[N_BB * N_C];

// ---------------------------------------------------------------------------
// prep: s,f,g = conv1x1(x) for both branches. Output layout [C][N] (k-major for GEMM).
// grid (32 n-tiles, 8 bb), 256 threads, dynamic smem 82688B.
// ---------------------------------------------------------------------------
__global__ __launch_bounds__(256) void prep_kernel(
    const float* __restrict__ student, const float* __restrict__ teacher,
    const float* __restrict__ si_w, const float* __restrict__ si_b,
    const float* __restrict__ fi_w, const float* __restrict__ fi_b,
    const float* __restrict__ gi_w, const float* __restrict__ gi_b)
{
    extern __shared__ float sm[];
    float* sX = sm;                    // [64][128]
    float* sW = sm + 8192;             // [3][64][64]
    float* sB = sm + 8192 + 12288;     // [3][64]
    const int tid = threadIdx.x;
    const int ntile = blockIdx.x, bb = blockIdx.y;
    const float* x = (bb < 4 ? student : teacher) + (size_t)(bb & 3) * N_C * N_SP;
    const int nbase = ntile * 128;

    for (int i = tid; i < 8192; i += 256) {
        int c = i >> 7, j = i & 127;
        sX[i] = x[(size_t)c * N_SP + nbase + j];
    }
    for (int i = tid; i < 4096; i += 256) {
        sW[i]        = si_w[i];
        sW[4096 + i] = fi_w[i];
        sW[8192 + i] = gi_w[i];
    }
    if (tid < 64) { sB[tid] = si_b[tid]; sB[64 + tid] = fi_b[tid]; sB[128 + tid] = gi_b[tid]; }
    __syncthreads();

    // conflict-free column split: this thread handles n0v..n0v+3 and n0v+64..n0v+67
    const int d0 = (tid >> 4) * 4, n0v = (tid & 15) * 4;
    #pragma unroll
    for (int mat = 0; mat < 3; ++mat) {
        const float* W = sW + mat * 4096;
        float acc[4][8];
        #pragma unroll
        for (int i = 0; i < 4; ++i)
            #pragma unroll
            for (int j = 0; j < 8; ++j) acc[i][j] = 0.f;

        #pragma unroll 4
        for (int k = 0; k < 64; ++k) {
            float4 x0 = *(const float4*)&sX[k * 128 + n0v];
            float4 x1 = *(const float4*)&sX[k * 128 + n0v + 64];
            float xv[8] = {x0.x, x0.y, x0.z, x0.w, x1.x, x1.y, x1.z, x1.w};
            #pragma unroll
            for (int i = 0; i < 4; ++i) {
                float wv = W[(d0 + i) * 64 + k];
                #pragma unroll
                for (int j = 0; j < 8; ++j) acc[i][j] = fmaf(wv, xv[j], acc[i][j]);
            }
        }
        float* out = (mat == 0 ? g_s : (mat == 1 ? g_f : g_g)) + (size_t)bb * N_C * N_SP;
        #pragma unroll
        for (int i = 0; i < 4; ++i) {
            float bias = sB[mat * 64 + d0 + i];
            float4 o0 = make_float4(acc[i][0] + bias, acc[i][1] + bias, acc[i][2] + bias, acc[i][3] + bias);
            float4 o1 = make_float4(acc[i][4] + bias, acc[i][5] + bias, acc[i][6] + bias, acc[i][7] + bias);
            *(float4*)&out[(size_t)(d0 + i) * N_SP + nbase + n0v]      = o0;
            *(float4*)&out[(size_t)(d0 + i) * N_SP + nbase + n0v + 64] = o1;
        }
    }
}

// ---------------------------------------------------------------------------
// sumx: per-(bb,c) spatial sums of the raw inputs.
// ---------------------------------------------------------------------------
__global__ __launch_bounds__(128) void sumx_kernel(const float* __restrict__ student,
                                                   const float* __restrict__ teacher)
{
    __shared__ float red[128];
    const int tid = threadIdx.x;
    const int bx = blockIdx.x;         // 0..511
    const int bb = bx >> 6, c = bx & 63;
    const float* x = (bb < 4 ? student : teacher) + ((size_t)(bb & 3) * N_C + c) * N_SP;
    float s = 0.f;
    for (int i = tid; i < N_SP; i += 128) s += x[i];
    red[tid] = s; __syncthreads();
    for (int off = 64; off > 0; off >>= 1) {
        if (tid < off) red[tid] += red[tid + off];
        __syncthreads();
    }
    if (tid == 0) g_sumx[bb * 64 + c] = red[0];
}

// ---------------------------------------------------------------------------
// attn: flash pass over F = s^T f. 128x128 tiles, K=64, per-thread 8x8, online softmax.
// grid (32 row-tiles, 8 bb), 256 threads, dynamic smem 98304B, 2 CTAs/SM.
// ---------------------------------------------------------------------------
__device__ __forceinline__ void cp_async16(void* dst, const void* src) {
    unsigned s = (unsigned)__cvta_generic_to_shared(dst);
    asm volatile("cp.async.cg.shared.global [%0], [%1], 16;" :: "r"(s), "l"(src) : "memory");
}

__global__ __launch_bounds__(256, 2) void attn_kernel()
{
    extern __shared__ float sm[];
    float* sS = sm;            // [64][128]
    float* sF = sm + 8192;     // [2][64][128]
    const int tid = threadIdx.x;
    const int rowtile = blockIdx.x, bb = blockIdx.y;
    const float* S = g_s + (size_t)bb * N_C * N_SP;
    const float* F = g_f + (size_t)bb * N_C * N_SP;
    const int rbase = rowtile * 128;

    // prefetch F tile 0 via cp.async
    #pragma unroll
    for (int i = 0; i < 8; ++i) {
        int ci = tid + i * 256;
        int k = ci >> 5, q = (ci & 31) * 4;
        cp_async16(&sF[k * 128 + q], &F[(size_t)k * N_SP + q]);
    }
    asm volatile("cp.async.commit_group;" ::: "memory");

    // load resident S tile (rows k=0..63, cols rbase..rbase+127), coalesced
    #pragma unroll
    for (int i = 0; i < 8; ++i) {
        int ci = tid + i * 256;
        int k = ci >> 5, q = (ci & 31) * 4;
        *(float4*)&sS[k * 128 + q] = *(const float4*)&S[(size_t)k * N_SP + rbase + q];
    }

    // rows: r0..r0+7 (contiguous, needed for the rowwise output);
    // cols: c0v..c0v+3 and c0v+64..c0v+67 (split -> conflict-free LDS.128)
    const int r0 = (tid >> 4) * 8, c0v = (tid & 15) * 4;
    float rm[8], re[8];
    #pragma unroll
    for (int i = 0; i < 8; ++i) { rm[i] = -1e30f; re[i] = 0.f; }

    for (int j = 0; j < 32; ++j) {
        asm volatile("cp.async.wait_group 0;" ::: "memory");
        __syncthreads();   // tile j visible to all; all threads done with tile j-1's buffer

        if (j + 1 < 32) {
            float* buf = sF + ((j + 1) & 1) * 8192;
            const int cb = (j + 1) * 128;
            #pragma unroll
            for (int i = 0; i < 8; ++i) {
                int ci = tid + i * 256;
                int k = ci >> 5, q = (ci & 31) * 4;
                cp_async16(&buf[k * 128 + q], &F[(size_t)k * N_SP + cb + q]);
            }
            asm volatile("cp.async.commit_group;" ::: "memory");
        }

        const float* Bt = sF + (j & 1) * 8192;
        float acc[8][8];
        #pragma unroll
        for (int i = 0; i < 8; ++i)
            #pragma unroll
            for (int jj = 0; jj < 8; ++jj) acc[i][jj] = 0.f;

        #pragma unroll 8
        for (int k = 0; k < 64; ++k) {
            float4 a0 = *(const float4*)&sS[k * 128 + r0];
            float4 a1 = *(const float4*)&sS[k * 128 + r0 + 4];
            float4 b0 = *(const float4*)&Bt[k * 128 + c0v];
            float4 b1 = *(const float4*)&Bt[k * 128 + c0v + 64];
            float av[8] = {a0.x, a0.y, a0.z, a0.w, a1.x, a1.y, a1.z, a1.w};
            float bv[8] = {b0.x, b0.y, b0.z, b0.w, b1.x, b1.y, b1.z, b1.w};
            #pragma unroll
            for (int i = 0; i < 8; ++i)
                #pragma unroll
                for (int jj = 0; jj < 8; ++jj)
                    acc[i][jj] = fmaf(av[i], bv[jj], acc[i][jj]);
        }

        // online softmax update over this thread's 8 columns of each of its 8 rows
        // (column identity is irrelevant: only row max / exp-sum are kept)
        #pragma unroll
        for (int i = 0; i < 8; ++i) {
            float tm = acc[i][0];
            #pragma unroll
            for (int jj = 1; jj < 8; ++jj) tm = fmaxf(tm, acc[i][jj]);
            float nm = fmaxf(rm[i], tm);
            float s = 0.f;
            #pragma unroll
            for (int jj = 0; jj < 8; ++jj) s += __expf(acc[i][jj] - nm);
            re[i] = re[i] * __expf(rm[i] - nm) + s;
            rm[i] = nm;
        }
    }

    // combine (m,e) across the 16 threads sharing each row (contiguous 16-lane groups)
    #pragma unroll
    for (int i = 0; i < 8; ++i) {
        float m = rm[i], e = re[i];
        #pragma unroll
        for (int off = 1; off < 16; off <<= 1) {
            float om = __shfl_xor_sync(0xffffffffu, m, off);
            float oe = __shfl_xor_sync(0xffffffffu, e, off);
            float nm = fmaxf(m, om);
            e = e * __expf(m - nm) + oe * __expf(om - nm);
            m = nm;
        }
        if ((tid & 15) == 0) {
            g_rowM[bb * N_SP + rbase + r0 + i] = m;
            g_rowE[bb * N_SP + rbase + r0 + i] = e;
        }
    }
}

// ---------------------------------------------------------------------------
// reduce_q: per (bb): global softmax combine -> row weights w_n, then q[c] = sum_n g[c,n] w_n
// ---------------------------------------------------------------------------
__global__ __launch_bounds__(256) void reduce_q_kernel()
{
    __shared__ float sw[N_SP];
    __shared__ float red[256];
    __shared__ float sq[4][64];
    const int tid = threadIdx.x;
    const int bb = blockIdx.x;
    const float* rM = g_rowM + bb * N_SP;
    const float* rE = g_rowE + bb * N_SP;

    float m = -1e30f;
    for (int i = tid; i < N_SP; i += 256) m = fmaxf(m, rM[i]);
    red[tid] = m; __syncthreads();
    for (int off = 128; off > 0; off >>= 1) {
        if (tid < off) red[tid] = fmaxf(red[tid], red[tid + off]);
        __syncthreads();
    }
    const float M = red[0];
    __syncthreads();

    float z = 0.f;
    for (int i = tid; i < N_SP; i += 256) {
        float w = rE[i] * __expf(rM[i] - M);
        sw[i] = w; z += w;
    }
    red[tid] = z; __syncthreads();
    for (int off = 128; off > 0; off >>= 1) {
        if (tid < off) red[tid] += red[tid + off];
        __syncthreads();
    }
    const float invZ = 1.f / red[0];

    const int c = tid & 63, seg = tid >> 6;
    const float* gp = g_g + (size_t)bb * N_C * N_SP + (size_t)c * N_SP + seg * 1024;
    const float* wp = sw + seg * 1024;
    float p = 0.f;
    #pragma unroll 4
    for (int i = 0; i < 1024; ++i) p = fmaf(gp[i], wp[i], p);
    sq[seg][c] = p;
    __syncthreads();
    if (tid < 64)
        g_q[bb * 64 + tid] = (sq[0][tid] + sq[1][tid] + sq[2][tid] + sq[3][tid]) * invZ;
}

// ---------------------------------------------------------------------------
// loss: out[b,c] per branch, MSE-sum, scale. One CTA, 256 threads = (b,c) pairs.
// ---------------------------------------------------------------------------
__global__ __launch_bounds__(256) void loss_kernel(const float* __restrict__ fsg_w,
                                                   const float* __restrict__ fsg_b,
                                                   float* __restrict__ out, int out_size)
{
    __shared__ float red[256];
    const int tid = threadIdx.x;
    const int b = tid >> 6, d = tid & 63;
    float dot_s = 0.f, dot_t = 0.f;
    #pragma unroll 8
    for (int c = 0; c < 64; ++c) {
        float w = fsg_w[d * 64 + c];
        dot_s = fmaf(w, g_q[b * 64 + c], dot_s);
        dot_t = fmaf(w, g_q[(4 + b) * 64 + c], dot_t);
    }
    const float invN = 1.f / 4096.f;
    float out_s = g_sumx[b * 64 + d] * invN + dot_s * invN + fsg_b[d];
    float out_t = g_sumx[(4 + b) * 64 + d] * invN + dot_t * invN + fsg_b[d];
    float diff = out_s - out_t;
    red[tid] = diff * diff;
    __syncthreads();
    for (int off = 128; off > 0; off >>= 1) {
        if (tid < off) red[tid] += red[tid + off];
        __syncthreads();
    }
    const float nlB = 0.05f * 4e-4f * red[0];        // non_loss * B
    for (int i = tid; i < out_size; i += 256)
        out[i] = (i == 0) ? nlB : nlB * 0.25f;       // [non_loss*B, non_loss]
}

// ---------------------------------------------------------------------------
extern "C" void kernel_launch(void* const* d_in, const int* in_sizes, int n_in,
                              void* d_out, int out_size)
{
    (void)in_sizes; (void)n_in;
    const float* student = (const float*)d_in[0];
    const float* teacher = (const float*)d_in[1];
    const float* si_w  = (const float*)d_in[2];
    const float* si_b  = (const float*)d_in[3];
    const float* fi_w  = (const float*)d_in[4];
    const float* fi_b  = (const float*)d_in[5];
    const float* gi_w  = (const float*)d_in[6];
    const float* gi_b  = (const float*)d_in[7];
    const float* fsg_w = (const float*)d_in[8];
    const float* fsg_b = (const float*)d_in[9];

    cudaFuncSetAttribute(prep_kernel, cudaFuncAttributeMaxDynamicSharedMemorySize, 82688);
    cudaFuncSetAttribute(attn_kernel, cudaFuncAttributeMaxDynamicSharedMemorySize, 98304);

    prep_kernel<<<dim3(32, 8), 256, 82688>>>(student, teacher, si_w, si_b, fi_w, fi_b, gi_w, gi_b);
    sumx_kernel<<<512, 128>>>(student, teacher);
    attn_kernel<<<dim3(32, 8), 256, 98304>>>();
    reduce_q_kernel<<<8, 256>>>();
    loss_kernel<<<1, 256>>>(fsg_w, fsg_b, (float*)d_out, out_size);
}

// round 5
// speedup vs baseline: 1.1941x; 1.1941x over previous
#include <cuda_runtime.h>

// NonLocalLoss: B=4, C=64, N=64*64=4096, two branches (student/teacher) sharing weights.
// out[b,c] = mean_n x + (fsg_w @ q)/N + fsg_b ; q[c] = sum_n g[c,n]*w_n
// w_n = rowsum_n of softmax over flattened F = s^T f. Flash-style single pass over F.

#define N_SP 4096
#define N_C  64
#define N_BB 8   // (branch*4 + batch)

// Scratch (device globals are the allowed scratch mechanism)
__device__ float g_s[(size_t)N_BB * N_C * N_SP];   // s in [C][N] layout per bb
__device__ float g_f[(size_t)N_BB * N_C * N_SP];   // f in [C][N]
__device__ float g_g[(size_t)N_BB * N_C * N_SP];   // g in [C][N]
__device__ float g_rowM[N_BB * N_SP];
__device__ float g_rowE[N_BB * N_SP];
__device__ float g_w[N_BB * N_SP];                 // normalized row weights
__device__ float g_q[N_BB * N_C];
__device__ float g_sumx[N_BB * N_C];

// ---------------------------------------------------------------------------
// prep: s,f,g = conv1x1(x) for both branches. Output layout [C][N] (k-major for GEMM).
// grid (32 n-tiles, 8 bb), 256 threads, dynamic smem 82688B.
// ---------------------------------------------------------------------------
__global__ __launch_bounds__(256) void prep_kernel(
    const float* __restrict__ student, const float* __restrict__ teacher,
    const float* __restrict__ si_w, const float* __restrict__ si_b,
    const float* __restrict__ fi_w, const float* __restrict__ fi_b,
    const float* __restrict__ gi_w, const float* __restrict__ gi_b)
{
    extern __shared__ float sm[];
    float* sX = sm;                    // [64][128]
    float* sW = sm + 8192;             // [3][64][64]
    float* sB = sm + 8192 + 12288;     // [3][64]
    const int tid = threadIdx.x;
    const int ntile = blockIdx.x, bb = blockIdx.y;
    const float* x = (bb < 4 ? student : teacher) + (size_t)(bb & 3) * N_C * N_SP;
    const int nbase = ntile * 128;

    for (int i = tid; i < 8192; i += 256) {
        int c = i >> 7, j = i & 127;
        sX[i] = x[(size_t)c * N_SP + nbase + j];
    }
    for (int i = tid; i < 4096; i += 256) {
        sW[i]        = si_w[i];
        sW[4096 + i] = fi_w[i];
        sW[8192 + i] = gi_w[i];
    }
    if (tid < 64) { sB[tid] = si_b[tid]; sB[64 + tid] = fi_b[tid]; sB[128 + tid] = gi_b[tid]; }
    __syncthreads();

    const int d0 = (tid >> 4) * 4, n0v = (tid & 15) * 4;
    #pragma unroll
    for (int mat = 0; mat < 3; ++mat) {
        const float* W = sW + mat * 4096;
        float acc[4][8];
        #pragma unroll
        for (int i = 0; i < 4; ++i)
            #pragma unroll
            for (int j = 0; j < 8; ++j) acc[i][j] = 0.f;

        #pragma unroll 4
        for (int k = 0; k < 64; ++k) {
            float4 x0 = *(const float4*)&sX[k * 128 + n0v];
            float4 x1 = *(const float4*)&sX[k * 128 + n0v + 64];
            float xv[8] = {x0.x, x0.y, x0.z, x0.w, x1.x, x1.y, x1.z, x1.w};
            #pragma unroll
            for (int i = 0; i < 4; ++i) {
                float wv = W[(d0 + i) * 64 + k];
                #pragma unroll
                for (int j = 0; j < 8; ++j) acc[i][j] = fmaf(wv, xv[j], acc[i][j]);
            }
        }
        float* out = (mat == 0 ? g_s : (mat == 1 ? g_f : g_g)) + (size_t)bb * N_C * N_SP;
        #pragma unroll
        for (int i = 0; i < 4; ++i) {
            float bias = sB[mat * 64 + d0 + i];
            float4 o0 = make_float4(acc[i][0] + bias, acc[i][1] + bias, acc[i][2] + bias, acc[i][3] + bias);
            float4 o1 = make_float4(acc[i][4] + bias, acc[i][5] + bias, acc[i][6] + bias, acc[i][7] + bias);
            *(float4*)&out[(size_t)(d0 + i) * N_SP + nbase + n0v]      = o0;
            *(float4*)&out[(size_t)(d0 + i) * N_SP + nbase + n0v + 64] = o1;
        }
    }
}

// ---------------------------------------------------------------------------
// sumx: per-(bb,c) spatial sums of the raw inputs.
// ---------------------------------------------------------------------------
__global__ __launch_bounds__(128) void sumx_kernel(const float* __restrict__ student,
                                                   const float* __restrict__ teacher)
{
    __shared__ float red[128];
    const int tid = threadIdx.x;
    const int bx = blockIdx.x;         // 0..511
    const int bb = bx >> 6, c = bx & 63;
    const float* x = (bb < 4 ? student : teacher) + ((size_t)(bb & 3) * N_C + c) * N_SP;
    float s = 0.f;
    for (int i = tid; i < N_SP; i += 128) s += x[i];
    red[tid] = s; __syncthreads();
    for (int off = 64; off > 0; off >>= 1) {
        if (tid < off) red[tid] += red[tid + off];
        __syncthreads();
    }
    if (tid == 0) g_sumx[bb * 64 + c] = red[0];
}

// ---------------------------------------------------------------------------
// attn: flash pass over F = s^T f. 128x128 tiles, K=64, per-thread 8x8 via
// packed fma.rn.f32x2 (FFMA2). S tile stored DUPLICATED in smem so one LDS.64
// yields {a,a}; F pairs come naturally from LDS.128 as aligned u64 pairs.
// grid (32 row-tiles, 8 bb), 256 threads, dynamic smem 131072B, 1 CTA/SM.
// ---------------------------------------------------------------------------
__device__ __forceinline__ void cp_async16(void* dst, const void* src) {
    unsigned s = (unsigned)__cvta_generic_to_shared(dst);
    asm volatile("cp.async.cg.shared.global [%0], [%1], 16;" :: "r"(s), "l"(src) : "memory");
}

#define FMA2(c, a, b) asm("fma.rn.f32x2 %0, %1, %2, %0;" : "+l"(c) : "l"(a), "l"(b))

__device__ __forceinline__ void unpack2(unsigned long long p, float& lo, float& hi) {
    asm("mov.b64 {%0, %1}, %2;" : "=f"(lo), "=f"(hi) : "l"(p));
}

__global__ __launch_bounds__(256, 1) void attn_kernel()
{
    extern __shared__ float sm[];
    float* sS2 = sm;             // [64][256] duplicated S tile (64 KB)
    float* sF  = sm + 16384;     // [2][64][128] F double buffer (64 KB)
    const int tid = threadIdx.x;
    const int rowtile = blockIdx.x, bb = blockIdx.y;
    const float* S = g_s + (size_t)bb * N_C * N_SP;
    const float* F = g_f + (size_t)bb * N_C * N_SP;
    const int rbase = rowtile * 128;

    // prefetch F tile 0 via cp.async
    #pragma unroll
    for (int i = 0; i < 8; ++i) {
        int ci = tid + i * 256;
        int k = ci >> 5, q = (ci & 31) * 4;
        cp_async16(&sF[k * 128 + q], &F[(size_t)k * N_SP + q]);
    }
    asm volatile("cp.async.commit_group;" ::: "memory");

    // load resident S tile, duplicated: sS2[k][2r] = sS2[k][2r+1] = S[k][rbase+r]
    #pragma unroll
    for (int i = 0; i < 8; ++i) {
        int ci = tid + i * 256;
        int k = ci >> 5, q = (ci & 31) * 4;
        float4 v = *(const float4*)&S[(size_t)k * N_SP + rbase + q];
        float2* d = (float2*)&sS2[k * 256 + 2 * q];
        d[0] = make_float2(v.x, v.x);
        d[1] = make_float2(v.y, v.y);
        d[2] = make_float2(v.z, v.z);
        d[3] = make_float2(v.w, v.w);
    }

    // rows r0..r0+7; cols c0v..c0v+3 and c0v+64..c0v+67 (column identity irrelevant)
    const int r0 = (tid >> 4) * 8, c0v = (tid & 15) * 4;
    float rm[8], re[8];
    #pragma unroll
    for (int i = 0; i < 8; ++i) { rm[i] = -1e30f; re[i] = 0.f; }

    for (int j = 0; j < 32; ++j) {
        asm volatile("cp.async.wait_group 0;" ::: "memory");
        __syncthreads();   // tile j visible; all threads done with buffer j-1

        if (j + 1 < 32) {
            float* buf = sF + ((j + 1) & 1) * 8192;
            const int cb = (j + 1) * 128;
            #pragma unroll
            for (int i = 0; i < 8; ++i) {
                int ci = tid + i * 256;
                int k = ci >> 5, q = (ci & 31) * 4;
                cp_async16(&buf[k * 128 + q], &F[(size_t)k * N_SP + cb + q]);
            }
            asm volatile("cp.async.commit_group;" ::: "memory");
        }

        const float* Bt = sF + (j & 1) * 8192;
        unsigned long long acc2[8][4];
        #pragma unroll
        for (int i = 0; i < 8; ++i)
            #pragma unroll
            for (int jp = 0; jp < 4; ++jp) acc2[i][jp] = 0ull;

        #pragma unroll 8
        for (int k = 0; k < 64; ++k) {
            // B pairs: two LDS.128, each gives two aligned {b_j, b_j+1} u64 pairs
            ulonglong2 bA = *(const ulonglong2*)&Bt[k * 128 + c0v];
            ulonglong2 bB = *(const ulonglong2*)&Bt[k * 128 + c0v + 64];
            // A dups: LDS.64 of duplicated S -> {a_i, a_i}
            unsigned long long a2[8];
            #pragma unroll
            for (int i = 0; i < 8; ++i)
                a2[i] = *(const unsigned long long*)&sS2[k * 256 + 2 * (r0 + i)];
            #pragma unroll
            for (int i = 0; i < 8; ++i) {
                FMA2(acc2[i][0], a2[i], bA.x);
                FMA2(acc2[i][1], a2[i], bA.y);
                FMA2(acc2[i][2], a2[i], bB.x);
                FMA2(acc2[i][3], a2[i], bB.y);
            }
        }

        // online softmax update (row max / exp-sum only)
        #pragma unroll
        for (int i = 0; i < 8; ++i) {
            float v[8];
            unpack2(acc2[i][0], v[0], v[1]);
            unpack2(acc2[i][1], v[2], v[3]);
            unpack2(acc2[i][2], v[4], v[5]);
            unpack2(acc2[i][3], v[6], v[7]);
            float tm = v[0];
            #pragma unroll
            for (int jj = 1; jj < 8; ++jj) tm = fmaxf(tm, v[jj]);
            float nm = fmaxf(rm[i], tm);
            float s = 0.f;
            #pragma unroll
            for (int jj = 0; jj < 8; ++jj) s += __expf(v[jj] - nm);
            re[i] = re[i] * __expf(rm[i] - nm) + s;
            rm[i] = nm;
        }
    }

    // combine (m,e) across the 16 threads sharing each row
    #pragma unroll
    for (int i = 0; i < 8; ++i) {
        float m = rm[i], e = re[i];
        #pragma unroll
        for (int off = 1; off < 16; off <<= 1) {
            float om = __shfl_xor_sync(0xffffffffu, m, off);
            float oe = __shfl_xor_sync(0xffffffffu, e, off);
            float nm = fmaxf(m, om);
            e = e * __expf(m - nm) + oe * __expf(om - nm);
            m = nm;
        }
        if ((tid & 15) == 0) {
            g_rowM[bb * N_SP + rbase + r0 + i] = m;
            g_rowE[bb * N_SP + rbase + r0 + i] = e;
        }
    }
}

// ---------------------------------------------------------------------------
// rowweight: per bb, global softmax combine -> normalized row weights g_w[bb][n]
// ---------------------------------------------------------------------------
__global__ __launch_bounds__(256) void rowweight_kernel()
{
    __shared__ float sw[N_SP];
    __shared__ float red[256];
    const int tid = threadIdx.x;
    const int bb = blockIdx.x;
    const float* rM = g_rowM + bb * N_SP;
    const float* rE = g_rowE + bb * N_SP;

    float m = -1e30f;
    for (int i = tid; i < N_SP; i += 256) m = fmaxf(m, rM[i]);
    red[tid] = m; __syncthreads();
    for (int off = 128; off > 0; off >>= 1) {
        if (tid < off) red[tid] = fmaxf(red[tid], red[tid + off]);
        __syncthreads();
    }
    const float M = red[0];
    __syncthreads();

    float z = 0.f;
    for (int i = tid; i < N_SP; i += 256) {
        float w = rE[i] * __expf(rM[i] - M);
        sw[i] = w; z += w;
    }
    red[tid] = z; __syncthreads();
    for (int off = 128; off > 0; off >>= 1) {
        if (tid < off) red[tid] += red[tid + off];
        __syncthreads();
    }
    const float invZ = 1.f / red[0];
    for (int i = tid; i < N_SP; i += 256)
        g_w[bb * N_SP + i] = sw[i] * invZ;
}

// ---------------------------------------------------------------------------
// qdot: one CTA per (bb,c): q[bb][c] = sum_n g[bb][c][n] * w[bb][n]. grid 512.
// ---------------------------------------------------------------------------
__global__ __launch_bounds__(128) void qdot_kernel()
{
    __shared__ float red[4];
    const int tid = threadIdx.x;
    const int blk = blockIdx.x;        // 0..511
    const int bb = blk >> 6, c = blk & 63;
    const float4* gp = (const float4*)(g_g + (size_t)bb * N_C * N_SP + (size_t)c * N_SP);
    const float4* wp = (const float4*)(g_w + bb * N_SP);
    float p = 0.f;
    #pragma unroll 2
    for (int i = tid; i < 1024; i += 128) {
        float4 a = gp[i], b = wp[i];
        p = fmaf(a.x, b.x, p); p = fmaf(a.y, b.y, p);
        p = fmaf(a.z, b.z, p); p = fmaf(a.w, b.w, p);
    }
    #pragma unroll
    for (int off = 16; off > 0; off >>= 1) p += __shfl_xor_sync(0xffffffffu, p, off);
    if ((tid & 31) == 0) red[tid >> 5] = p;
    __syncthreads();
    if (tid == 0)
        g_q[bb * 64 + c] = red[0] + red[1] + red[2] + red[3];
}

// ---------------------------------------------------------------------------
// loss: out[b,c] per branch, MSE-sum, scale. One CTA, 256 threads = (b,c) pairs.
// ---------------------------------------------------------------------------
__global__ __launch_bounds__(256) void loss_kernel(const float* __restrict__ fsg_w,
                                                   const float* __restrict__ fsg_b,
                                                   float* __restrict__ out, int out_size)
{
    __shared__ float red[256];
    const int tid = threadIdx.x;
    const int b = tid >> 6, d = tid & 63;
    float dot_s = 0.f, dot_t = 0.f;
    #pragma unroll 8
    for (int c = 0; c < 64; ++c) {
        float w = fsg_w[d * 64 + c];
        dot_s = fmaf(w, g_q[b * 64 + c], dot_s);
        dot_t = fmaf(w, g_q[(4 + b) * 64 + c], dot_t);
    }
    const float invN = 1.f / 4096.f;
    float out_s = g_sumx[b * 64 + d] * invN + dot_s * invN + fsg_b[d];
    float out_t = g_sumx[(4 + b) * 64 + d] * invN + dot_t * invN + fsg_b[d];
    float diff = out_s - out_t;
    red[tid] = diff * diff;
    __syncthreads();
    for (int off = 128; off > 0; off >>= 1) {
        if (tid < off) red[tid] += red[tid + off];
        __syncthreads();
    }
    const float nlB = 0.05f * 4e-4f * red[0];        // non_loss * B
    for (int i = tid; i < out_size; i += 256)
        out[i] = (i == 0) ? nlB : nlB * 0.25f;       // [non_loss*B, non_loss]
}

// ---------------------------------------------------------------------------
extern "C" void kernel_launch(void* const* d_in, const int* in_sizes, int n_in,
                              void* d_out, int out_size)
{
    (void)in_sizes; (void)n_in;
    const float* student = (const float*)d_in[0];
    const float* teacher = (const float*)d_in[1];
    const float* si_w  = (const float*)d_in[2];
    const float* si_b  = (const float*)d_in[3];
    const float* fi_w  = (const float*)d_in[4];
    const float* fi_b  = (const float*)d_in[5];
    const float* gi_w  = (const float*)d_in[6];
    const float* gi_b  = (const float*)d_in[7];
    const float* fsg_w = (const float*)d_in[8];
    const float* fsg_b = (const float*)d_in[9];

    cudaFuncSetAttribute(prep_kernel, cudaFuncAttributeMaxDynamicSharedMemorySize, 82688);
    cudaFuncSetAttribute(attn_kernel, cudaFuncAttributeMaxDynamicSharedMemorySize, 131072);

    prep_kernel<<<dim3(32, 8), 256, 82688>>>(student, teacher, si_w, si_b, fi_w, fi_b, gi_w, gi_b);
    sumx_kernel<<<512, 128>>>(student, teacher);
    attn_kernel<<<dim3(32, 8), 256, 131072>>>();
    rowweight_kernel<<<8, 256>>>();
    qdot_kernel<<<512, 128>>>();
    loss_kernel<<<1, 256>>>(fsg_w, fsg_b, (float*)d_out, out_size);
}

// round 6
// speedup vs baseline: 1.4799x; 1.2393x over previous
#include <cuda_runtime.h>

// NonLocalLoss: B=4, C=64, N=4096, two branches sharing weights.
// out[b,c] = mean_n x + (fsg_w @ q)/N + fsg_b ; q[c] = (sum_n g[c,n]*E_n)/Z
// E_n = sum_m 2^(F'_nm - 64), F' = (log2e*s)^T f, Z = sum_n E_n  (flat softmax,
// shift-invariant => identical to reference softmax over the flattened matrix).

#define N_SP 4096
#define N_C  64
#define N_BB 8

__device__ float g_s[(size_t)N_BB * N_C * N_SP];   // s*log2e, [C][N] per bb
__device__ float g_f[(size_t)N_BB * N_C * N_SP];
__device__ float g_g[(size_t)N_BB * N_C * N_SP];
__device__ float g_rowE[N_BB * N_SP];
__device__ float g_q[N_BB * N_C];
__device__ float g_sumx[N_BB * N_C];

// ---------------------------------------------------------------------------
// prep: s,f,g = conv1x1(x). s path pre-scaled by log2(e). Layout [C][N].
// ---------------------------------------------------------------------------
__global__ __launch_bounds__(256) void prep_kernel(
    const float* __restrict__ student, const float* __restrict__ teacher,
    const float* __restrict__ si_w, const float* __restrict__ si_b,
    const float* __restrict__ fi_w, const float* __restrict__ fi_b,
    const float* __restrict__ gi_w, const float* __restrict__ gi_b)
{
    extern __shared__ float sm[];
    float* sX = sm;                    // [64][128]
    float* sW = sm + 8192;             // [3][64][64]
    float* sB = sm + 8192 + 12288;     // [3][64]
    const int tid = threadIdx.x;
    const int ntile = blockIdx.x, bb = blockIdx.y;
    const float* x = (bb < 4 ? student : teacher) + (size_t)(bb & 3) * N_C * N_SP;
    const int nbase = ntile * 128;
    const float LOG2E = 1.4426950408889634f;

    for (int i = tid; i < 8192; i += 256) {
        int c = i >> 7, j = i & 127;
        sX[i] = x[(size_t)c * N_SP + nbase + j];
    }
    for (int i = tid; i < 4096; i += 256) {
        sW[i]        = si_w[i] * LOG2E;   // fold log2e into s path
        sW[4096 + i] = fi_w[i];
        sW[8192 + i] = gi_w[i];
    }
    if (tid < 64) {
        sB[tid]       = si_b[tid] * LOG2E;
        sB[64 + tid]  = fi_b[tid];
        sB[128 + tid] = gi_b[tid];
    }
    __syncthreads();

    const int d0 = (tid >> 4) * 4, n0v = (tid & 15) * 4;
    #pragma unroll
    for (int mat = 0; mat < 3; ++mat) {
        const float* W = sW + mat * 4096;
        float acc[4][8];
        #pragma unroll
        for (int i = 0; i < 4; ++i)
            #pragma unroll
            for (int j = 0; j < 8; ++j) acc[i][j] = 0.f;

        #pragma unroll 4
        for (int k = 0; k < 64; ++k) {
            float4 x0 = *(const float4*)&sX[k * 128 + n0v];
            float4 x1 = *(const float4*)&sX[k * 128 + n0v + 64];
            float xv[8] = {x0.x, x0.y, x0.z, x0.w, x1.x, x1.y, x1.z, x1.w};
            #pragma unroll
            for (int i = 0; i < 4; ++i) {
                float wv = W[(d0 + i) * 64 + k];
                #pragma unroll
                for (int j = 0; j < 8; ++j) acc[i][j] = fmaf(wv, xv[j], acc[i][j]);
            }
        }
        float* out = (mat == 0 ? g_s : (mat == 1 ? g_f : g_g)) + (size_t)bb * N_C * N_SP;
        #pragma unroll
        for (int i = 0; i < 4; ++i) {
            float bias = sB[mat * 64 + d0 + i];
            float4 o0 = make_float4(acc[i][0] + bias, acc[i][1] + bias, acc[i][2] + bias, acc[i][3] + bias);
            float4 o1 = make_float4(acc[i][4] + bias, acc[i][5] + bias, acc[i][6] + bias, acc[i][7] + bias);
            *(float4*)&out[(size_t)(d0 + i) * N_SP + nbase + n0v]      = o0;
            *(float4*)&out[(size_t)(d0 + i) * N_SP + nbase + n0v + 64] = o1;
        }
    }
}

// ---------------------------------------------------------------------------
// sumx: per-(bb,c) spatial sums of the raw inputs.
// ---------------------------------------------------------------------------
__global__ __launch_bounds__(128) void sumx_kernel(const float* __restrict__ student,
                                                   const float* __restrict__ teacher)
{
    __shared__ float red[128];
    const int tid = threadIdx.x;
    const int bx = blockIdx.x;
    const int bb = bx >> 6, c = bx & 63;
    const float* x = (bb < 4 ? student : teacher) + ((size_t)(bb & 3) * N_C + c) * N_SP;
    float s = 0.f;
    for (int i = tid; i < N_SP; i += 128) s += x[i];
    red[tid] = s; __syncthreads();
    for (int off = 64; off > 0; off >>= 1) {
        if (tid < off) red[tid] += red[tid + off];
        __syncthreads();
    }
    if (tid == 0) g_sumx[bb * 64 + c] = red[0];
}

// ---------------------------------------------------------------------------
// attn: F' = (log2e*s)^T f, accumulate E_n = sum_m 2^(F'-64). 128x128 tiles,
// FFMA2 mainloop, A pairs built by register packing (ALU pipe, overlaps FMA).
// grid (32, 8), 256 threads, smem 98304B -> 2 CTAs/SM, 256 CTAs = 1 wave.
// ---------------------------------------------------------------------------
__device__ __forceinline__ void cp_async16(void* dst, const void* src) {
    unsigned s = (unsigned)__cvta_generic_to_shared(dst);
    asm volatile("cp.async.cg.shared.global [%0], [%1], 16;" :: "r"(s), "l"(src) : "memory");
}

#define FMA2(c, a, b) asm("fma.rn.f32x2 %0, %1, %2, %0;" : "+l"(c) : "l"(a), "l"(b))
#define ADD2(c, b)    asm("add.rn.f32x2 %0, %0, %1;" : "+l"(c) : "l"(b))

__device__ __forceinline__ unsigned long long pack2(float lo, float hi) {
    unsigned long long p;
    asm("mov.b64 %0, {%1, %2};" : "=l"(p) : "f"(lo), "f"(hi));
    return p;
}
__device__ __forceinline__ void unpack2(unsigned long long p, float& lo, float& hi) {
    asm("mov.b64 {%0, %1}, %2;" : "=f"(lo), "=f"(hi) : "l"(p));
}
__device__ __forceinline__ float ex2f(float x) {
    float r; asm("ex2.approx.ftz.f32 %0, %1;" : "=f"(r) : "f"(x)); return r;
}

__global__ __launch_bounds__(256, 2) void attn_kernel()
{
    extern __shared__ float sm[];
    float* sS = sm;            // [64][128] (32 KB)
    float* sF = sm + 8192;     // [2][64][128] (64 KB)
    const int tid = threadIdx.x;
    const int rowtile = blockIdx.x, bb = blockIdx.y;
    const float* S = g_s + (size_t)bb * N_C * N_SP;
    const float* F = g_f + (size_t)bb * N_C * N_SP;
    const int rbase = rowtile * 128;

    #pragma unroll
    for (int i = 0; i < 8; ++i) {
        int ci = tid + i * 256;
        int k = ci >> 5, q = (ci & 31) * 4;
        cp_async16(&sF[k * 128 + q], &F[(size_t)k * N_SP + q]);
    }
    asm volatile("cp.async.commit_group;" ::: "memory");

    #pragma unroll
    for (int i = 0; i < 8; ++i) {
        int ci = tid + i * 256;
        int k = ci >> 5, q = (ci & 31) * 4;
        *(float4*)&sS[k * 128 + q] = *(const float4*)&S[(size_t)k * N_SP + rbase + q];
    }

    const int r0 = (tid >> 4) * 8, c0v = (tid & 15) * 4;
    const unsigned long long SHIFT2 = pack2(-64.f, -64.f);
    float re[8];
    #pragma unroll
    for (int i = 0; i < 8; ++i) re[i] = 0.f;

    for (int j = 0; j < 32; ++j) {
        asm volatile("cp.async.wait_group 0;" ::: "memory");
        __syncthreads();

        if (j + 1 < 32) {
            float* buf = sF + ((j + 1) & 1) * 8192;
            const int cb = (j + 1) * 128;
            #pragma unroll
            for (int i = 0; i < 8; ++i) {
                int ci = tid + i * 256;
                int k = ci >> 5, q = (ci & 31) * 4;
                cp_async16(&buf[k * 128 + q], &F[(size_t)k * N_SP + cb + q]);
            }
            asm volatile("cp.async.commit_group;" ::: "memory");
        }

        const float* Bt = sF + (j & 1) * 8192;
        unsigned long long acc2[8][4];
        #pragma unroll
        for (int i = 0; i < 8; ++i)
            #pragma unroll
            for (int jp = 0; jp < 4; ++jp) acc2[i][jp] = 0ull;

        #pragma unroll 8
        for (int k = 0; k < 64; ++k) {
            ulonglong2 bA = *(const ulonglong2*)&Bt[k * 128 + c0v];
            ulonglong2 bB = *(const ulonglong2*)&Bt[k * 128 + c0v + 64];
            float4 aA = *(const float4*)&sS[k * 128 + r0];
            float4 aB = *(const float4*)&sS[k * 128 + r0 + 4];
            unsigned long long a2[8];
            a2[0] = pack2(aA.x, aA.x); a2[1] = pack2(aA.y, aA.y);
            a2[2] = pack2(aA.z, aA.z); a2[3] = pack2(aA.w, aA.w);
            a2[4] = pack2(aB.x, aB.x); a2[5] = pack2(aB.y, aB.y);
            a2[6] = pack2(aB.z, aB.z); a2[7] = pack2(aB.w, aB.w);
            #pragma unroll
            for (int i = 0; i < 8; ++i) {
                FMA2(acc2[i][0], a2[i], bA.x);
                FMA2(acc2[i][1], a2[i], bA.y);
                FMA2(acc2[i][2], a2[i], bB.x);
                FMA2(acc2[i][3], a2[i], bB.y);
            }
        }

        // flat-softmax accumulation: re += sum 2^(v - 64); no max tracking.
        #pragma unroll
        for (int i = 0; i < 8; ++i) {
            ADD2(acc2[i][0], SHIFT2); ADD2(acc2[i][1], SHIFT2);
            ADD2(acc2[i][2], SHIFT2); ADD2(acc2[i][3], SHIFT2);
            float v[8];
            unpack2(acc2[i][0], v[0], v[1]);
            unpack2(acc2[i][1], v[2], v[3]);
            unpack2(acc2[i][2], v[4], v[5]);
            unpack2(acc2[i][3], v[6], v[7]);
            float s = 0.f;
            #pragma unroll
            for (int jj = 0; jj < 8; ++jj) s += ex2f(v[jj]);
            re[i] += s;
        }
    }

    // sum E across the 16 threads sharing each row
    #pragma unroll
    for (int i = 0; i < 8; ++i) {
        float e = re[i];
        #pragma unroll
        for (int off = 1; off < 16; off <<= 1)
            e += __shfl_xor_sync(0xffffffffu, e, off);
        if ((tid & 15) == 0)
            g_rowE[bb * N_SP + rbase + r0 + i] = e;
    }
}

// ---------------------------------------------------------------------------
// qdot: one CTA per (bb,c): q = (sum_n g[c,n]*E_n) / (sum_n E_n). grid 512.
// Z computed redundantly per block (4096 adds, negligible).
// ---------------------------------------------------------------------------
__global__ __launch_bounds__(128) void qdot_kernel()
{
    __shared__ float redP[4], redZ[4];
    const int tid = threadIdx.x;
    const int blk = blockIdx.x;        // 0..511
    const int bb = blk >> 6, c = blk & 63;
    const float4* gp = (const float4*)(g_g + (size_t)bb * N_C * N_SP + (size_t)c * N_SP);
    const float4* ep = (const float4*)(g_rowE + bb * N_SP);
    float p = 0.f, z = 0.f;
    #pragma unroll 2
    for (int i = tid; i < 1024; i += 128) {
        float4 a = gp[i], e = ep[i];
        p = fmaf(a.x, e.x, p); p = fmaf(a.y, e.y, p);
        p = fmaf(a.z, e.z, p); p = fmaf(a.w, e.w, p);
        z += (e.x + e.y) + (e.z + e.w);
    }
    #pragma unroll
    for (int off = 16; off > 0; off >>= 1) {
        p += __shfl_xor_sync(0xffffffffu, p, off);
        z += __shfl_xor_sync(0xffffffffu, z, off);
    }
    if ((tid & 31) == 0) { redP[tid >> 5] = p; redZ[tid >> 5] = z; }
    __syncthreads();
    if (tid == 0) {
        float P = redP[0] + redP[1] + redP[2] + redP[3];
        float Z = redZ[0] + redZ[1] + redZ[2] + redZ[3];
        g_q[bb * 64 + c] = P / Z;
    }
}

// ---------------------------------------------------------------------------
// loss: out[b,c] per branch, MSE-sum, scale.
// ---------------------------------------------------------------------------
__global__ __launch_bounds__(256) void loss_kernel(const float* __restrict__ fsg_w,
                                                   const float* __restrict__ fsg_b,
                                                   float* __restrict__ out, int out_size)
{
    __shared__ float red[256];
    const int tid = threadIdx.x;
    const int b = tid >> 6, d = tid & 63;
    float dot_s = 0.f, dot_t = 0.f;
    #pragma unroll 8
    for (int c = 0; c < 64; ++c) {
        float w = fsg_w[d * 64 + c];
        dot_s = fmaf(w, g_q[b * 64 + c], dot_s);
        dot_t = fmaf(w, g_q[(4 + b) * 64 + c], dot_t);
    }
    const float invN = 1.f / 4096.f;
    float out_s = g_sumx[b * 64 + d] * invN + dot_s * invN + fsg_b[d];
    float out_t = g_sumx[(4 + b) * 64 + d] * invN + dot_t * invN + fsg_b[d];
    float diff = out_s - out_t;
    red[tid] = diff * diff;
    __syncthreads();
    for (int off = 128; off > 0; off >>= 1) {
        if (tid < off) red[tid] += red[tid + off];
        __syncthreads();
    }
    const float nlB = 0.05f * 4e-4f * red[0];        // non_loss * B
    for (int i = tid; i < out_size; i += 256)
        out[i] = (i == 0) ? nlB : nlB * 0.25f;       // [non_loss*B, non_loss]
}

// ---------------------------------------------------------------------------
extern "C" void kernel_launch(void* const* d_in, const int* in_sizes, int n_in,
                              void* d_out, int out_size)
{
    (void)in_sizes; (void)n_in;
    const float* student = (const float*)d_in[0];
    const float* teacher = (const float*)d_in[1];
    const float* si_w  = (const float*)d_in[2];
    const float* si_b  = (const float*)d_in[3];
    const float* fi_w  = (const float*)d_in[4];
    const float* fi_b  = (const float*)d_in[5];
    const float* gi_w  = (const float*)d_in[6];
    const float* gi_b  = (const float*)d_in[7];
    const float* fsg_w = (const float*)d_in[8];
    const float* fsg_b = (const float*)d_in[9];

    cudaFuncSetAttribute(prep_kernel, cudaFuncAttributeMaxDynamicSharedMemorySize, 82688);
    cudaFuncSetAttribute(attn_kernel, cudaFuncAttributeMaxDynamicSharedMemorySize, 98304);

    prep_kernel<<<dim3(32, 8), 256, 82688>>>(student, teacher, si_w, si_b, fi_w, fi_b, gi_w, gi_b);
    sumx_kernel<<<512, 128>>>(student, teacher);
    attn_kernel<<<dim3(32, 8), 256, 98304>>>();
    qdot_kernel<<<512, 128>>>();
    loss_kernel<<<1, 256>>>(fsg_w, fsg_b, (float*)d_out, out_size);
}

// round 8
// speedup vs baseline: 2.7501x; 1.8583x over previous
#include <cuda_runtime.h>
#include <cuda_bf16.h>
#include <cstdint>

// NonLocalLoss: B=4, C=64, N=4096, two branches sharing weights.
// out[b,c] = mean_n x + (fsg_w @ q)/N + fsg_b ; q[c] = (sum_n g[c,n]*E_n)/Z
// E_n = sum_m 2^(F'_nm), F' = (log2e*s)^T f  (flat softmax, shift-invariant).
// F' on warp-level mma.sync bf16 (sm_100-safe), split-precision hi+lo (3 MMAs).

#define N_SP 4096
#define N_C  64
#define N_BB 8

// bf16 operands in [n][c] layout (K-major for MMA), per bb
__device__ __nv_bfloat16 g_s_hi[(size_t)N_BB * N_SP * N_C];
__device__ __nv_bfloat16 g_s_lo[(size_t)N_BB * N_SP * N_C];
__device__ __nv_bfloat16 g_f_hi[(size_t)N_BB * N_SP * N_C];
__device__ __nv_bfloat16 g_f_lo[(size_t)N_BB * N_SP * N_C];
__device__ float g_g[(size_t)N_BB * N_C * N_SP];   // fp32 [C][N]
__device__ float g_rowE[N_BB * N_SP];
__device__ float g_q[N_BB * N_C];
__device__ float g_sumx[N_BB * N_C];

// ---------------------------------------------------------------------------
// prep: s,f,g = conv1x1(x). s scaled by log2e. s,f stored transposed bf16 hi/lo.
// ---------------------------------------------------------------------------
__global__ __launch_bounds__(256) void prep_kernel(
    const float* __restrict__ student, const float* __restrict__ teacher,
    const float* __restrict__ si_w, const float* __restrict__ si_b,
    const float* __restrict__ fi_w, const float* __restrict__ fi_b,
    const float* __restrict__ gi_w, const float* __restrict__ gi_b)
{
    extern __shared__ float sm[];
    float* sX = sm;                    // [64][128]
    float* sW = sm + 8192;             // [3][64][64]
    float* sB = sm + 8192 + 12288;     // [3][64]
    const int tid = threadIdx.x;
    const int ntile = blockIdx.x, bb = blockIdx.y;
    const float* x = (bb < 4 ? student : teacher) + (size_t)(bb & 3) * N_C * N_SP;
    const int nbase = ntile * 128;
    const float LOG2E = 1.4426950408889634f;

    for (int i = tid; i < 8192; i += 256) {
        int c = i >> 7, j = i & 127;
        sX[i] = x[(size_t)c * N_SP + nbase + j];
    }
    for (int i = tid; i < 4096; i += 256) {
        sW[i]        = si_w[i] * LOG2E;
        sW[4096 + i] = fi_w[i];
        sW[8192 + i] = gi_w[i];
    }
    if (tid < 64) {
        sB[tid]       = si_b[tid] * LOG2E;
        sB[64 + tid]  = fi_b[tid];
        sB[128 + tid] = gi_b[tid];
    }
    __syncthreads();

    const int d0 = (tid >> 4) * 4, n0v = (tid & 15) * 4;
    #pragma unroll
    for (int mat = 0; mat < 3; ++mat) {
        const float* W = sW + mat * 4096;
        float acc[4][8];
        #pragma unroll
        for (int i = 0; i < 4; ++i)
            #pragma unroll
            for (int j = 0; j < 8; ++j) acc[i][j] = 0.f;

        #pragma unroll 4
        for (int k = 0; k < 64; ++k) {
            float4 x0 = *(const float4*)&sX[k * 128 + n0v];
            float4 x1 = *(const float4*)&sX[k * 128 + n0v + 64];
            float xv[8] = {x0.x, x0.y, x0.z, x0.w, x1.x, x1.y, x1.z, x1.w};
            #pragma unroll
            for (int i = 0; i < 4; ++i) {
                float wv = W[(d0 + i) * 64 + k];
                #pragma unroll
                for (int j = 0; j < 8; ++j) acc[i][j] = fmaf(wv, xv[j], acc[i][j]);
            }
        }
        if (mat < 2) {
            // transposed bf16 hi/lo store: [n][c], 4 consecutive c per 8B store
            __nv_bfloat16* outH = (mat == 0 ? g_s_hi : g_f_hi) + (size_t)bb * N_SP * N_C;
            __nv_bfloat16* outL = (mat == 0 ? g_s_lo : g_f_lo) + (size_t)bb * N_SP * N_C;
            #pragma unroll
            for (int j = 0; j < 8; ++j) {
                int n = nbase + n0v + (j < 4 ? j : 60 + j);   // n0v+{0..3}, n0v+64+{0..3}
                float v0 = acc[0][j] + sB[mat * 64 + d0 + 0];
                float v1 = acc[1][j] + sB[mat * 64 + d0 + 1];
                float v2 = acc[2][j] + sB[mat * 64 + d0 + 2];
                float v3 = acc[3][j] + sB[mat * 64 + d0 + 3];
                __nv_bfloat16 h0 = __float2bfloat16(v0), h1 = __float2bfloat16(v1);
                __nv_bfloat16 h2 = __float2bfloat16(v2), h3 = __float2bfloat16(v3);
                __nv_bfloat16 l0 = __float2bfloat16(v0 - __bfloat162float(h0));
                __nv_bfloat16 l1 = __float2bfloat16(v1 - __bfloat162float(h1));
                __nv_bfloat16 l2 = __float2bfloat16(v2 - __bfloat162float(h2));
                __nv_bfloat16 l3 = __float2bfloat16(v3 - __bfloat162float(h3));
                unsigned hi01 = (unsigned)__bfloat16_as_ushort(h0) | ((unsigned)__bfloat16_as_ushort(h1) << 16);
                unsigned hi23 = (unsigned)__bfloat16_as_ushort(h2) | ((unsigned)__bfloat16_as_ushort(h3) << 16);
                unsigned lo01 = (unsigned)__bfloat16_as_ushort(l0) | ((unsigned)__bfloat16_as_ushort(l1) << 16);
                unsigned lo23 = (unsigned)__bfloat16_as_ushort(l2) | ((unsigned)__bfloat16_as_ushort(l3) << 16);
                *(uint2*)&outH[(size_t)n * N_C + d0] = make_uint2(hi01, hi23);
                *(uint2*)&outL[(size_t)n * N_C + d0] = make_uint2(lo01, lo23);
            }
        } else {
            float* out = g_g + (size_t)bb * N_C * N_SP;
            #pragma unroll
            for (int i = 0; i < 4; ++i) {
                float bias = sB[mat * 64 + d0 + i];
                float4 o0 = make_float4(acc[i][0] + bias, acc[i][1] + bias, acc[i][2] + bias, acc[i][3] + bias);
                float4 o1 = make_float4(acc[i][4] + bias, acc[i][5] + bias, acc[i][6] + bias, acc[i][7] + bias);
                *(float4*)&out[(size_t)(d0 + i) * N_SP + nbase + n0v]      = o0;
                *(float4*)&out[(size_t)(d0 + i) * N_SP + nbase + n0v + 64] = o1;
            }
        }
    }
}

// ---------------------------------------------------------------------------
// sumx: per-(bb,c) spatial sums of the raw inputs.
// ---------------------------------------------------------------------------
__global__ __launch_bounds__(128) void sumx_kernel(const float* __restrict__ student,
                                                   const float* __restrict__ teacher)
{
    __shared__ float red[128];
    const int tid = threadIdx.x;
    const int bx = blockIdx.x;
    const int bb = bx >> 6, c = bx & 63;
    const float* x = (bb < 4 ? student : teacher) + ((size_t)(bb & 3) * N_C + c) * N_SP;
    float s = 0.f;
    for (int i = tid; i < N_SP; i += 128) s += x[i];
    red[tid] = s; __syncthreads();
    for (int off = 64; off > 0; off >>= 1) {
        if (tid < off) red[tid] += red[tid + off];
        __syncthreads();
    }
    if (tid == 0) g_sumx[bb * 64 + c] = red[0];
}

// ---------------------------------------------------------------------------
// attn helpers
// ---------------------------------------------------------------------------
__device__ __forceinline__ uint32_t smem_u32(const void* p) {
    uint32_t a;
    asm("{ .reg .u64 t; cvta.to.shared.u64 t, %1; cvt.u32.u64 %0, t; }" : "=r"(a) : "l"(p));
    return a;
}
__device__ __forceinline__ void cp_async16s(uint32_t dst, const void* src) {
    asm volatile("cp.async.cg.shared.global [%0], [%1], 16;" :: "r"(dst), "l"(src) : "memory");
}
__device__ __forceinline__ float ex2f(float x) {
    float r; asm("ex2.approx.ftz.f32 %0, %1;" : "=f"(r) : "f"(x)); return r;
}
#define MMA16816(c, a, b0, b1) \
    asm volatile("mma.sync.aligned.m16n8k16.row.col.f32.bf16.bf16.f32 " \
        "{%0,%1,%2,%3}, {%4,%5,%6,%7}, {%8,%9}, {%0,%1,%2,%3};" \
        : "+f"((c)[0]), "+f"((c)[1]), "+f"((c)[2]), "+f"((c)[3]) \
        : "r"((a)[0]), "r"((a)[1]), "r"((a)[2]), "r"((a)[3]), "r"(b0), "r"(b1))

// B tile smem: [2 bufs][2 halves][128 rows][72 bf16]  (stride 72 = conflict-free frags)
#define B_ROWSTR 72
#define B_HALF   (128 * B_ROWSTR * 2)      // bytes per half = 18432
#define B_BUF    (2 * B_HALF)              // bytes per buffer = 36864

// ---------------------------------------------------------------------------
// attn: F' via mma.sync split-bf16 (aH*bH + aL*bH + aH*bL, 3 independent
// 4-deep chains). Accumulators in registers; epilogue = ex2 + row adds.
// grid (32 rowtiles, 8 bb), 256 threads, smem 73728B -> 2 CTA/SM, 1 wave.
// ---------------------------------------------------------------------------
__global__ __launch_bounds__(256, 2) void attn_kernel()
{
    extern __shared__ char rawsm[];
    const uint32_t base = smem_u32(rawsm);
    const int tid = threadIdx.x;
    const int wid = tid >> 5, lane = tid & 31;
    const int g = lane >> 2, t = lane & 3;
    const int rowtile = blockIdx.x, bb = blockIdx.y;
    const int rbase = rowtile * 128;
    const __nv_bfloat16* SH = g_s_hi + (size_t)bb * N_SP * N_C;
    const __nv_bfloat16* SL = g_s_lo + (size_t)bb * N_SP * N_C;
    const __nv_bfloat16* FH = g_f_hi + (size_t)bb * N_SP * N_C;
    const __nv_bfloat16* FL = g_f_lo + (size_t)bb * N_SP * N_C;

    // A fragments for this warp's 16 rows (resident in registers all kernel)
    uint32_t aH[4][4], aL[4][4];
    {
        const int r = rbase + 16 * wid + g;
        #pragma unroll
        for (int kb = 0; kb < 4; ++kb) {
            int k0 = 16 * kb + 2 * t;
            aH[kb][0] = *(const uint32_t*)&SH[(size_t)r * N_C + k0];
            aH[kb][1] = *(const uint32_t*)&SH[(size_t)(r + 8) * N_C + k0];
            aH[kb][2] = *(const uint32_t*)&SH[(size_t)r * N_C + k0 + 8];
            aH[kb][3] = *(const uint32_t*)&SH[(size_t)(r + 8) * N_C + k0 + 8];
            aL[kb][0] = *(const uint32_t*)&SL[(size_t)r * N_C + k0];
            aL[kb][1] = *(const uint32_t*)&SL[(size_t)(r + 8) * N_C + k0];
            aL[kb][2] = *(const uint32_t*)&SL[(size_t)r * N_C + k0 + 8];
            aL[kb][3] = *(const uint32_t*)&SL[(size_t)(r + 8) * N_C + k0 + 8];
        }
    }

    // prefetch B col-tiles 0 and 1
    #pragma unroll
    for (int p = 0; p < 2; ++p) {
        #pragma unroll
        for (int i = 0; i < 8; ++i) {
            int ci = tid + i * 256;                 // 0..2047
            int half = ci >> 10, rem = ci & 1023;
            int row = rem >> 3, ch = rem & 7;
            const __nv_bfloat16* src = (half ? FL : FH) + (size_t)(p * 128 + row) * N_C + ch * 8;
            cp_async16s(base + p * B_BUF + half * B_HALF + row * (B_ROWSTR * 2) + ch * 16, src);
        }
        asm volatile("cp.async.commit_group;" ::: "memory");
    }

    float e0 = 0.f, e1 = 0.f;

    for (int j = 0; j < 32; ++j) {
        asm volatile("cp.async.wait_group 1;" ::: "memory");
        __syncthreads();                            // tile j ready for all warps

        const char* bufH = rawsm + (j & 1) * B_BUF;
        const char* bufL = bufH + B_HALF;

        #pragma unroll 2
        for (int nt = 0; nt < 16; ++nt) {
            const uint32_t* pH = (const uint32_t*)(bufH + (nt * 8 + g) * (B_ROWSTR * 2));
            const uint32_t* pL = (const uint32_t*)(bufL + (nt * 8 + g) * (B_ROWSTR * 2));
            float cA[4] = {0.f, 0.f, 0.f, 0.f};
            float cB[4] = {0.f, 0.f, 0.f, 0.f};
            float cC[4] = {0.f, 0.f, 0.f, 0.f};
            #pragma unroll
            for (int kb = 0; kb < 4; ++kb) {
                uint32_t bh0 = pH[8 * kb + t];
                uint32_t bh1 = pH[8 * kb + t + 4];
                uint32_t bl0 = pL[8 * kb + t];
                uint32_t bl1 = pL[8 * kb + t + 4];
                MMA16816(cA, aH[kb], bh0, bh1);
                MMA16816(cB, aL[kb], bh0, bh1);
                MMA16816(cC, aH[kb], bl0, bl1);
            }
            e0 += ex2f(cA[0] + cB[0] + cC[0]) + ex2f(cA[1] + cB[1] + cC[1]);
            e1 += ex2f(cA[2] + cB[2] + cC[2]) + ex2f(cA[3] + cB[3] + cC[3]);
        }

        __syncthreads();                            // all warps done with buffer j
        if (j + 2 < 32) {
            const int cb = (j + 2) * 128;
            #pragma unroll
            for (int i = 0; i < 8; ++i) {
                int ci = tid + i * 256;
                int half = ci >> 10, rem = ci & 1023;
                int row = rem >> 3, ch = rem & 7;
                const __nv_bfloat16* src = (half ? FL : FH) + (size_t)(cb + row) * N_C + ch * 8;
                cp_async16s(base + (j & 1) * B_BUF + half * B_HALF + row * (B_ROWSTR * 2) + ch * 16, src);
            }
            asm volatile("cp.async.commit_group;" ::: "memory");
        }
    }

    // reduce over the 4 lanes (t) sharing each row; rows: rbase+16w+g, +8
    e0 += __shfl_xor_sync(0xffffffffu, e0, 1);
    e0 += __shfl_xor_sync(0xffffffffu, e0, 2);
    e1 += __shfl_xor_sync(0xffffffffu, e1, 1);
    e1 += __shfl_xor_sync(0xffffffffu, e1, 2);
    if (t == 0) {
        g_rowE[bb * N_SP + rbase + 16 * wid + g]     = e0;
        g_rowE[bb * N_SP + rbase + 16 * wid + g + 8] = e1;
    }
}

// ---------------------------------------------------------------------------
// qdot: one CTA per (bb,c): q = (sum_n g[c,n]*E_n) / (sum_n E_n). grid 512.
// ---------------------------------------------------------------------------
__global__ __launch_bounds__(128) void qdot_kernel()
{
    __shared__ float redP[4], redZ[4];
    const int tid = threadIdx.x;
    const int blk = blockIdx.x;
    const int bb = blk >> 6, c = blk & 63;
    const float4* gp = (const float4*)(g_g + (size_t)bb * N_C * N_SP + (size_t)c * N_SP);
    const float4* ep = (const float4*)(g_rowE + bb * N_SP);
    float p = 0.f, z = 0.f;
    #pragma unroll 2
    for (int i = tid; i < 1024; i += 128) {
        float4 a = gp[i], e = ep[i];
        p = fmaf(a.x, e.x, p); p = fmaf(a.y, e.y, p);
        p = fmaf(a.z, e.z, p); p = fmaf(a.w, e.w, p);
        z += (e.x + e.y) + (e.z + e.w);
    }
    #pragma unroll
    for (int off = 16; off > 0; off >>= 1) {
        p += __shfl_xor_sync(0xffffffffu, p, off);
        z += __shfl_xor_sync(0xffffffffu, z, off);
    }
    if ((tid & 31) == 0) { redP[tid >> 5] = p; redZ[tid >> 5] = z; }
    __syncthreads();
    if (tid == 0) {
        float P = redP[0] + redP[1] + redP[2] + redP[3];
        float Z = redZ[0] + redZ[1] + redZ[2] + redZ[3];
        g_q[bb * 64 + c] = P / Z;
    }
}

// ---------------------------------------------------------------------------
// loss: out[b,c] per branch, MSE-sum, scale.
// ---------------------------------------------------------------------------
__global__ __launch_bounds__(256) void loss_kernel(const float* __restrict__ fsg_w,
                                                   const float* __restrict__ fsg_b,
                                                   float* __restrict__ out, int out_size)
{
    __shared__ float red[256];
    const int tid = threadIdx.x;
    const int b = tid >> 6, d = tid & 63;
    float dot_s = 0.f, dot_t = 0.f;
    #pragma unroll 8
    for (int c = 0; c < 64; ++c) {
        float w = fsg_w[d * 64 + c];
        dot_s = fmaf(w, g_q[b * 64 + c], dot_s);
        dot_t = fmaf(w, g_q[(4 + b) * 64 + c], dot_t);
    }
    const float invN = 1.f / 4096.f;
    float out_s = g_sumx[b * 64 + d] * invN + dot_s * invN + fsg_b[d];
    float out_t = g_sumx[(4 + b) * 64 + d] * invN + dot_t * invN + fsg_b[d];
    float diff = out_s - out_t;
    red[tid] = diff * diff;
    __syncthreads();
    for (int off = 128; off > 0; off >>= 1) {
        if (tid < off) red[tid] += red[tid + off];
        __syncthreads();
    }
    const float nlB = 0.05f * 4e-4f * red[0];        // non_loss * B
    for (int i = tid; i < out_size; i += 256)
        out[i] = (i == 0) ? nlB : nlB * 0.25f;       // [non_loss*B, non_loss]
}

// ---------------------------------------------------------------------------
extern "C" void kernel_launch(void* const* d_in, const int* in_sizes, int n_in,
                              void* d_out, int out_size)
{
    (void)in_sizes; (void)n_in;
    const float* student = (const float*)d_in[0];
    const float* teacher = (const float*)d_in[1];
    const float* si_w  = (const float*)d_in[2];
    const float* si_b  = (const float*)d_in[3];
    const float* fi_w  = (const float*)d_in[4];
    const float* fi_b  = (const float*)d_in[5];
    const float* gi_w  = (const float*)d_in[6];
    const float* gi_b  = (const float*)d_in[7];
    const float* fsg_w = (const float*)d_in[8];
    const float* fsg_b = (const float*)d_in[9];

    cudaFuncSetAttribute(prep_kernel, cudaFuncAttributeMaxDynamicSharedMemorySize, 82688);
    cudaFuncSetAttribute(attn_kernel, cudaFuncAttributeMaxDynamicSharedMemorySize, 2 * B_BUF);

    prep_kernel<<<dim3(32, 8), 256, 82688>>>(student, teacher, si_w, si_b, fi_w, fi_b, gi_w, gi_b);
    sumx_kernel<<<512, 128>>>(student, teacher);
    attn_kernel<<<dim3(32, 8), 256, 2 * B_BUF>>>();
    qdot_kernel<<<512, 128>>>();
    loss_kernel<<<1, 256>>>(fsg_w, fsg_b, (float*)d_out, out_size);
}

// round 9
// speedup vs baseline: 2.7902x; 1.0146x over previous
#include <cuda_runtime.h>
#include <cuda_bf16.h>
#include <cstdint>

// NonLocalLoss: B=4, C=64, N=4096, two branches sharing weights.
// out[b,c] = mean_n x + (fsg_w @ q)/N + fsg_b ; q[c] = (sum_n g[c,n]*E_n)/Z
// E_n = sum_m 2^(F'_nm), F' = (log2e*s)^T f  (flat softmax, shift-invariant).
// F' on warp-level mma.sync bf16 (sm_100-safe), split-precision hi+lo (3 MMAs).
// f stored in mma-fragment-native fused layout: 1 LDS.128 = all 4 B regs.

#define N_SP 4096
#define N_C  64
#define N_BB 8

// s in [n][c] bf16 hi/lo (A operand, loaded to regs once per CTA)
__device__ __nv_bfloat16 g_s_hi[(size_t)N_BB * N_SP * N_C];
__device__ __nv_bfloat16 g_s_lo[(size_t)N_BB * N_SP * N_C];
// f fused fragment layout: per row n, 256 B; group (kb,t) at (kb*4+t)*16:
//   bytes 0-3: hi k=16kb+2t,2t+1 | 4-7: hi k=16kb+8+2t,+1 | 8-15: same lo
__device__ uint8_t g_f_fused[(size_t)N_BB * N_SP * 256];
__device__ float g_g[(size_t)N_BB * N_C * N_SP];   // fp32 [C][N]
__device__ float g_rowE[N_BB * N_SP];
__device__ float g_q[N_BB * N_C];
__device__ float g_sumx[N_BB * N_C];

// ---------------------------------------------------------------------------
// prep: s,f,g = conv1x1(x). s scaled by log2e -> [n][c] hi/lo; f -> fused layout.
// ---------------------------------------------------------------------------
__global__ __launch_bounds__(256) void prep_kernel(
    const float* __restrict__ student, const float* __restrict__ teacher,
    const float* __restrict__ si_w, const float* __restrict__ si_b,
    const float* __restrict__ fi_w, const float* __restrict__ fi_b,
    const float* __restrict__ gi_w, const float* __restrict__ gi_b)
{
    extern __shared__ float sm[];
    float* sX = sm;                    // [64][128]
    float* sW = sm + 8192;             // [3][64][64]
    float* sB = sm + 8192 + 12288;     // [3][64]
    const int tid = threadIdx.x;
    const int ntile = blockIdx.x, bb = blockIdx.y;
    const float* x = (bb < 4 ? student : teacher) + (size_t)(bb & 3) * N_C * N_SP;
    const int nbase = ntile * 128;
    const float LOG2E = 1.4426950408889634f;

    for (int i = tid; i < 8192; i += 256) {
        int c = i >> 7, j = i & 127;
        sX[i] = x[(size_t)c * N_SP + nbase + j];
    }
    for (int i = tid; i < 4096; i += 256) {
        sW[i]        = si_w[i] * LOG2E;
        sW[4096 + i] = fi_w[i];
        sW[8192 + i] = gi_w[i];
    }
    if (tid < 64) {
        sB[tid]       = si_b[tid] * LOG2E;
        sB[64 + tid]  = fi_b[tid];
        sB[128 + tid] = gi_b[tid];
    }
    __syncthreads();

    const int d0 = (tid >> 4) * 4, n0v = (tid & 15) * 4;
    #pragma unroll
    for (int mat = 0; mat < 3; ++mat) {
        const float* W = sW + mat * 4096;
        float acc[4][8];
        #pragma unroll
        for (int i = 0; i < 4; ++i)
            #pragma unroll
            for (int j = 0; j < 8; ++j) acc[i][j] = 0.f;

        #pragma unroll 4
        for (int k = 0; k < 64; ++k) {
            float4 x0 = *(const float4*)&sX[k * 128 + n0v];
            float4 x1 = *(const float4*)&sX[k * 128 + n0v + 64];
            float xv[8] = {x0.x, x0.y, x0.z, x0.w, x1.x, x1.y, x1.z, x1.w};
            #pragma unroll
            for (int i = 0; i < 4; ++i) {
                float wv = W[(d0 + i) * 64 + k];
                #pragma unroll
                for (int j = 0; j < 8; ++j) acc[i][j] = fmaf(wv, xv[j], acc[i][j]);
            }
        }
        if (mat < 2) {
            #pragma unroll
            for (int j = 0; j < 8; ++j) {
                int n = nbase + n0v + (j < 4 ? j : 60 + j);   // n0v+{0..3}, n0v+64+{0..3}
                float v0 = acc[0][j] + sB[mat * 64 + d0 + 0];
                float v1 = acc[1][j] + sB[mat * 64 + d0 + 1];
                float v2 = acc[2][j] + sB[mat * 64 + d0 + 2];
                float v3 = acc[3][j] + sB[mat * 64 + d0 + 3];
                __nv_bfloat16 h0 = __float2bfloat16(v0), h1 = __float2bfloat16(v1);
                __nv_bfloat16 h2 = __float2bfloat16(v2), h3 = __float2bfloat16(v3);
                __nv_bfloat16 l0 = __float2bfloat16(v0 - __bfloat162float(h0));
                __nv_bfloat16 l1 = __float2bfloat16(v1 - __bfloat162float(h1));
                __nv_bfloat16 l2 = __float2bfloat16(v2 - __bfloat162float(h2));
                __nv_bfloat16 l3 = __float2bfloat16(v3 - __bfloat162float(h3));
                unsigned hi01 = (unsigned)__bfloat16_as_ushort(h0) | ((unsigned)__bfloat16_as_ushort(h1) << 16);
                unsigned hi23 = (unsigned)__bfloat16_as_ushort(h2) | ((unsigned)__bfloat16_as_ushort(h3) << 16);
                unsigned lo01 = (unsigned)__bfloat16_as_ushort(l0) | ((unsigned)__bfloat16_as_ushort(l1) << 16);
                unsigned lo23 = (unsigned)__bfloat16_as_ushort(l2) | ((unsigned)__bfloat16_as_ushort(l3) << 16);
                if (mat == 0) {
                    __nv_bfloat16* outH = g_s_hi + (size_t)bb * N_SP * N_C;
                    __nv_bfloat16* outL = g_s_lo + (size_t)bb * N_SP * N_C;
                    *(uint2*)&outH[(size_t)n * N_C + d0] = make_uint2(hi01, hi23);
                    *(uint2*)&outL[(size_t)n * N_C + d0] = make_uint2(lo01, lo23);
                } else {
                    // fused fragment layout for f
                    uint8_t* fF = g_f_fused + (size_t)bb * N_SP * 256 + (size_t)n * 256;
                    const int kb  = d0 >> 4;
                    const int w0  = d0 & 15;
                    const int tt0 = (w0 & 7) >> 1;       // pair0 -> t=tt0, pair1 -> t=tt0+1
                    const int hi4 = (w0 & 8) ? 4 : 0;    // second k-octet slot
                    *(unsigned*)(fF + (kb * 4 + tt0) * 16 + hi4)         = hi01;
                    *(unsigned*)(fF + (kb * 4 + tt0) * 16 + hi4 + 8)     = lo01;
                    *(unsigned*)(fF + (kb * 4 + tt0 + 1) * 16 + hi4)     = hi23;
                    *(unsigned*)(fF + (kb * 4 + tt0 + 1) * 16 + hi4 + 8) = lo23;
                }
            }
        } else {
            float* out = g_g + (size_t)bb * N_C * N_SP;
            #pragma unroll
            for (int i = 0; i < 4; ++i) {
                float bias = sB[mat * 64 + d0 + i];
                float4 o0 = make_float4(acc[i][0] + bias, acc[i][1] + bias, acc[i][2] + bias, acc[i][3] + bias);
                float4 o1 = make_float4(acc[i][4] + bias, acc[i][5] + bias, acc[i][6] + bias, acc[i][7] + bias);
                *(float4*)&out[(size_t)(d0 + i) * N_SP + nbase + n0v]      = o0;
                *(float4*)&out[(size_t)(d0 + i) * N_SP + nbase + n0v + 64] = o1;
            }
        }
    }
}

// ---------------------------------------------------------------------------
// sumx: per-(bb,c) spatial sums of the raw inputs.
// ---------------------------------------------------------------------------
__global__ __launch_bounds__(128) void sumx_kernel(const float* __restrict__ student,
                                                   const float* __restrict__ teacher)
{
    __shared__ float red[128];
    const int tid = threadIdx.x;
    const int bx = blockIdx.x;
    const int bb = bx >> 6, c = bx & 63;
    const float* x = (bb < 4 ? student : teacher) + ((size_t)(bb & 3) * N_C + c) * N_SP;
    float s = 0.f;
    for (int i = tid; i < N_SP; i += 128) s += x[i];
    red[tid] = s; __syncthreads();
    for (int off = 64; off > 0; off >>= 1) {
        if (tid < off) red[tid] += red[tid + off];
        __syncthreads();
    }
    if (tid == 0) g_sumx[bb * 64 + c] = red[0];
}

// ---------------------------------------------------------------------------
// attn helpers
// ---------------------------------------------------------------------------
__device__ __forceinline__ uint32_t smem_u32(const void* p) {
    uint32_t a;
    asm("{ .reg .u64 t; cvta.to.shared.u64 t, %1; cvt.u32.u64 %0, t; }" : "=r"(a) : "l"(p));
    return a;
}
__device__ __forceinline__ void cp_async16s(uint32_t dst, const void* src) {
    asm volatile("cp.async.cg.shared.global [%0], [%1], 16;" :: "r"(dst), "l"(src) : "memory");
}
__device__ __forceinline__ float ex2f(float x) {
    float r; asm("ex2.approx.ftz.f32 %0, %1;" : "=f"(r) : "f"(x)); return r;
}
#define MMA16816(c, a, b0, b1) \
    asm volatile("mma.sync.aligned.m16n8k16.row.col.f32.bf16.bf16.f32 " \
        "{%0,%1,%2,%3}, {%4,%5,%6,%7}, {%8,%9}, {%0,%1,%2,%3};" \
        : "+f"((c)[0]), "+f"((c)[1]), "+f"((c)[2]), "+f"((c)[3]) \
        : "r"((a)[0]), "r"((a)[1]), "r"((a)[2]), "r"((a)[3]), "r"(b0), "r"(b1))

// B tile smem: 128 rows x 320 B (256 data + 64 pad; 320 % 128 == 64 -> LDS.128
// quarter-warp phases conflict-free). Two buffers.
#define B_ROWSTR 320
#define B_BUF    (128 * B_ROWSTR)          // 40960 B

// ---------------------------------------------------------------------------
// attn: per warp 32 rows (2 m16 blocks, A resident in regs), CTA = 256 rows.
// Per (nt,kb): 1 LDS.128 -> {bh0,bh1,bl0,bl1} feeds 6 mmas (2 blocks x 3 prods).
// grid (16 rowtiles, 8 bb) = 128 CTAs, 256 thr, smem 81920B, 1 CTA/SM, 1 wave.
// ---------------------------------------------------------------------------
__global__ __launch_bounds__(256, 1) void attn_kernel()
{
    extern __shared__ char rawsm[];
    const uint32_t base = smem_u32(rawsm);
    const int tid = threadIdx.x;
    const int wid = tid >> 5, lane = tid & 31;
    const int g = lane >> 2, t = lane & 3;
    const int rowtile = blockIdx.x, bb = blockIdx.y;
    const int rbase = rowtile * 256;
    const __nv_bfloat16* SH = g_s_hi + (size_t)bb * N_SP * N_C;
    const __nv_bfloat16* SL = g_s_lo + (size_t)bb * N_SP * N_C;
    const uint8_t* FF = g_f_fused + (size_t)bb * N_SP * 256;

    // A fragments: 2 row-blocks x 4 kb x 4 regs, hi+lo (resident)
    uint32_t aH[2][4][4], aL[2][4][4];
    {
        const int r0 = rbase + 32 * wid + g;
        #pragma unroll
        for (int rb = 0; rb < 2; ++rb) {
            const int ra = r0 + 16 * rb, rbot = ra + 8;
            #pragma unroll
            for (int kb = 0; kb < 4; ++kb) {
                const int k0 = 16 * kb + 2 * t;
                aH[rb][kb][0] = *(const uint32_t*)&SH[(size_t)ra * N_C + k0];
                aH[rb][kb][1] = *(const uint32_t*)&SH[(size_t)rbot * N_C + k0];
                aH[rb][kb][2] = *(const uint32_t*)&SH[(size_t)ra * N_C + k0 + 8];
                aH[rb][kb][3] = *(const uint32_t*)&SH[(size_t)rbot * N_C + k0 + 8];
                aL[rb][kb][0] = *(const uint32_t*)&SL[(size_t)ra * N_C + k0];
                aL[rb][kb][1] = *(const uint32_t*)&SL[(size_t)rbot * N_C + k0];
                aL[rb][kb][2] = *(const uint32_t*)&SL[(size_t)ra * N_C + k0 + 8];
                aL[rb][kb][3] = *(const uint32_t*)&SL[(size_t)rbot * N_C + k0 + 8];
            }
        }
    }

    // prefetch B col-tiles 0 and 1 (128 rows x 256 B each)
    #pragma unroll
    for (int p = 0; p < 2; ++p) {
        #pragma unroll
        for (int i = 0; i < 8; ++i) {
            int ci = tid + i * 256;                 // 0..2047
            int row = ci >> 4, ch = ci & 15;
            cp_async16s(base + p * B_BUF + row * B_ROWSTR + ch * 16,
                        FF + (size_t)(p * 128 + row) * 256 + ch * 16);
        }
        asm volatile("cp.async.commit_group;" ::: "memory");
    }

    float e00 = 0.f, e01 = 0.f, e10 = 0.f, e11 = 0.f;

    for (int j = 0; j < 32; ++j) {
        asm volatile("cp.async.wait_group 1;" ::: "memory");
        __syncthreads();                            // tile j ready for all warps

        const char* buf = rawsm + (j & 1) * B_BUF;

        #pragma unroll 2
        for (int nt = 0; nt < 16; ++nt) {
            const char* rowp = buf + (nt * 8 + g) * B_ROWSTR + t * 16;
            uint4 bv[4];
            #pragma unroll
            for (int kb = 0; kb < 4; ++kb)
                bv[kb] = *(const uint4*)(rowp + kb * 64);

            float cA0[4] = {0.f,0.f,0.f,0.f}, cB0[4] = {0.f,0.f,0.f,0.f}, cC0[4] = {0.f,0.f,0.f,0.f};
            float cA1[4] = {0.f,0.f,0.f,0.f}, cB1[4] = {0.f,0.f,0.f,0.f}, cC1[4] = {0.f,0.f,0.f,0.f};
            #pragma unroll
            for (int kb = 0; kb < 4; ++kb) {
                MMA16816(cA0, aH[0][kb], bv[kb].x, bv[kb].y);
                MMA16816(cA1, aH[1][kb], bv[kb].x, bv[kb].y);
                MMA16816(cB0, aL[0][kb], bv[kb].x, bv[kb].y);
                MMA16816(cB1, aL[1][kb], bv[kb].x, bv[kb].y);
                MMA16816(cC0, aH[0][kb], bv[kb].z, bv[kb].w);
                MMA16816(cC1, aH[1][kb], bv[kb].z, bv[kb].w);
            }
            e00 += ex2f(cA0[0] + cB0[0] + cC0[0]) + ex2f(cA0[1] + cB0[1] + cC0[1]);
            e01 += ex2f(cA0[2] + cB0[2] + cC0[2]) + ex2f(cA0[3] + cB0[3] + cC0[3]);
            e10 += ex2f(cA1[0] + cB1[0] + cC1[0]) + ex2f(cA1[1] + cB1[1] + cC1[1]);
            e11 += ex2f(cA1[2] + cB1[2] + cC1[2]) + ex2f(cA1[3] + cB1[3] + cC1[3]);
        }

        __syncthreads();                            // all warps done with buffer j
        if (j + 2 < 32) {
            const int cb = (j + 2) * 128;
            #pragma unroll
            for (int i = 0; i < 8; ++i) {
                int ci = tid + i * 256;
                int row = ci >> 4, ch = ci & 15;
                cp_async16s(base + (j & 1) * B_BUF + row * B_ROWSTR + ch * 16,
                            FF + (size_t)(cb + row) * 256 + ch * 16);
            }
            asm volatile("cp.async.commit_group;" ::: "memory");
        }
    }

    // reduce over the 4 lanes (t) sharing each row
    #pragma unroll
    for (int off = 1; off < 4; off <<= 1) {
        e00 += __shfl_xor_sync(0xffffffffu, e00, off);
        e01 += __shfl_xor_sync(0xffffffffu, e01, off);
        e10 += __shfl_xor_sync(0xffffffffu, e10, off);
        e11 += __shfl_xor_sync(0xffffffffu, e11, off);
    }
    if (t == 0) {
        const int rb0 = bb * N_SP + rbase + 32 * wid + g;
        g_rowE[rb0]      = e00;
        g_rowE[rb0 + 8]  = e01;
        g_rowE[rb0 + 16] = e10;
        g_rowE[rb0 + 24] = e11;
    }
}

// ---------------------------------------------------------------------------
// qdot: one CTA per (bb,c): q = (sum_n g[c,n]*E_n) / (sum_n E_n). grid 512.
// ---------------------------------------------------------------------------
__global__ __launch_bounds__(128) void qdot_kernel()
{
    __shared__ float redP[4], redZ[4];
    const int tid = threadIdx.x;
    const int blk = blockIdx.x;
    const int bb = blk >> 6, c = blk & 63;
    const float4* gp = (const float4*)(g_g + (size_t)bb * N_C * N_SP + (size_t)c * N_SP);
    const float4* ep = (const float4*)(g_rowE + bb * N_SP);
    float p = 0.f, z = 0.f;
    #pragma unroll 2
    for (int i = tid; i < 1024; i += 128) {
        float4 a = gp[i], e = ep[i];
        p = fmaf(a.x, e.x, p); p = fmaf(a.y, e.y, p);
        p = fmaf(a.z, e.z, p); p = fmaf(a.w, e.w, p);
        z += (e.x + e.y) + (e.z + e.w);
    }
    #pragma unroll
    for (int off = 16; off > 0; off >>= 1) {
        p += __shfl_xor_sync(0xffffffffu, p, off);
        z += __shfl_xor_sync(0xffffffffu, z, off);
    }
    if ((tid & 31) == 0) { redP[tid >> 5] = p; redZ[tid >> 5] = z; }
    __syncthreads();
    if (tid == 0) {
        float P = redP[0] + redP[1] + redP[2] + redP[3];
        float Z = redZ[0] + redZ[1] + redZ[2] + redZ[3];
        g_q[bb * 64 + c] = P / Z;
    }
}

// ---------------------------------------------------------------------------
// loss: out[b,c] per branch, MSE-sum, scale.
// ---------------------------------------------------------------------------
__global__ __launch_bounds__(256) void loss_kernel(const float* __restrict__ fsg_w,
                                                   const float* __restrict__ fsg_b,
                                                   float* __restrict__ out, int out_size)
{
    __shared__ float red[256];
    const int tid = threadIdx.x;
    const int b = tid >> 6, d = tid & 63;
    float dot_s = 0.f, dot_t = 0.f;
    #pragma unroll 8
    for (int c = 0; c < 64; ++c) {
        float w = fsg_w[d * 64 + c];
        dot_s = fmaf(w, g_q[b * 64 + c], dot_s);
        dot_t = fmaf(w, g_q[(4 + b) * 64 + c], dot_t);
    }
    const float invN = 1.f / 4096.f;
    float out_s = g_sumx[b * 64 + d] * invN + dot_s * invN + fsg_b[d];
    float out_t = g_sumx[(4 + b) * 64 + d] * invN + dot_t * invN + fsg_b[d];
    float diff = out_s - out_t;
    red[tid] = diff * diff;
    __syncthreads();
    for (int off = 128; off > 0; off >>= 1) {
        if (tid < off) red[tid] += red[tid + off];
        __syncthreads();
    }
    const float nlB = 0.05f * 4e-4f * red[0];        // non_loss * B
    for (int i = tid; i < out_size; i += 256)
        out[i] = (i == 0) ? nlB : nlB * 0.25f;       // [non_loss*B, non_loss]
}

// ---------------------------------------------------------------------------
extern "C" void kernel_launch(void* const* d_in, const int* in_sizes, int n_in,
                              void* d_out, int out_size)
{
    (void)in_sizes; (void)n_in;
    const float* student = (const float*)d_in[0];
    const float* teacher = (const float*)d_in[1];
    const float* si_w  = (const float*)d_in[2];
    const float* si_b  = (const float*)d_in[3];
    const float* fi_w  = (const float*)d_in[4];
    const float* fi_b  = (const float*)d_in[5];
    const float* gi_w  = (const float*)d_in[6];
    const float* gi_b  = (const float*)d_in[7];
    const float* fsg_w = (const float*)d_in[8];
    const float* fsg_b = (const float*)d_in[9];

    cudaFuncSetAttribute(prep_kernel, cudaFuncAttributeMaxDynamicSharedMemorySize, 82688);
    cudaFuncSetAttribute(attn_kernel, cudaFuncAttributeMaxDynamicSharedMemorySize, 2 * B_BUF);

    prep_kernel<<<dim3(32, 8), 256, 82688>>>(student, teacher, si_w, si_b, fi_w, fi_b, gi_w, gi_b);
    sumx_kernel<<<512, 128>>>(student, teacher);
    attn_kernel<<<dim3(16, 8), 256, 2 * B_BUF>>>();
    qdot_kernel<<<512, 128>>>();
    loss_kernel<<<1, 256>>>(fsg_w, fsg_b, (float*)d_out, out_size);
}

// round 10
// speedup vs baseline: 4.0477x; 1.4507x over previous
#include <cuda_runtime.h>
#include <cuda_fp16.h>
#include <cstdint>

// NonLocalLoss: B=4, C=64, N=4096, two branches sharing weights.
// out[b,c] = mean_n x + (fsg_w @ q)/N + fsg_b ; q[c] = (sum_n g[c,n]*E_n)/Z
// E_n = sum_m 2^(F'_nm), F' = (log2e*s)^T f  (flat softmax, shift-invariant).
// F' via mma.sync fp16 (sm_100-safe): A = s split EXACTLY into fp16 hi+lo
// (2 products), B = f single fp16 (only B-rounding error ~2^-11 -> ~0.2%
// softmax-weight error -> ~1e-5..1e-4 final loss error, tolerance 1e-3).

#define N_SP 4096
#define N_C  64
#define N_BB 8

// s in [n][c] fp16 hi/lo (A operand, loaded to regs once per CTA)
__device__ __half g_s_hi[(size_t)N_BB * N_SP * N_C];
__device__ __half g_s_lo[(size_t)N_BB * N_SP * N_C];
// f fused fragment layout: per row n, 128 B; group (kb,t) at (kb*4+t)*8:
//   bytes 0-3: fp16 k=16kb+2t,2t+1 | bytes 4-7: fp16 k=16kb+8+2t,+1
__device__ uint8_t g_f_fused[(size_t)N_BB * N_SP * 128];
__device__ float g_g[(size_t)N_BB * N_C * N_SP];   // fp32 [C][N]
__device__ float g_rowE[N_BB * N_SP];
__device__ float g_q[N_BB * N_C];
__device__ float g_sumx[N_BB * N_C];

// ---------------------------------------------------------------------------
// prep: s,f,g = conv1x1(x). s scaled by log2e -> [n][c] fp16 hi/lo;
// f -> fused fp16 fragment layout; g -> fp32 [C][N].
// ---------------------------------------------------------------------------
__global__ __launch_bounds__(256) void prep_kernel(
    const float* __restrict__ student, const float* __restrict__ teacher,
    const float* __restrict__ si_w, const float* __restrict__ si_b,
    const float* __restrict__ fi_w, const float* __restrict__ fi_b,
    const float* __restrict__ gi_w, const float* __restrict__ gi_b)
{
    extern __shared__ float sm[];
    float* sX = sm;                    // [64][128]
    float* sW = sm + 8192;             // [3][64][64]
    float* sB = sm + 8192 + 12288;     // [3][64]
    const int tid = threadIdx.x;
    const int ntile = blockIdx.x, bb = blockIdx.y;
    const float* x = (bb < 4 ? student : teacher) + (size_t)(bb & 3) * N_C * N_SP;
    const int nbase = ntile * 128;
    const float LOG2E = 1.4426950408889634f;

    for (int i = tid; i < 8192; i += 256) {
        int c = i >> 7, j = i & 127;
        sX[i] = x[(size_t)c * N_SP + nbase + j];
    }
    for (int i = tid; i < 4096; i += 256) {
        sW[i]        = si_w[i] * LOG2E;
        sW[4096 + i] = fi_w[i];
        sW[8192 + i] = gi_w[i];
    }
    if (tid < 64) {
        sB[tid]       = si_b[tid] * LOG2E;
        sB[64 + tid]  = fi_b[tid];
        sB[128 + tid] = gi_b[tid];
    }
    __syncthreads();

    const int d0 = (tid >> 4) * 4, n0v = (tid & 15) * 4;
    #pragma unroll
    for (int mat = 0; mat < 3; ++mat) {
        const float* W = sW + mat * 4096;
        float acc[4][8];
        #pragma unroll
        for (int i = 0; i < 4; ++i)
            #pragma unroll
            for (int j = 0; j < 8; ++j) acc[i][j] = 0.f;

        #pragma unroll 4
        for (int k = 0; k < 64; ++k) {
            float4 x0 = *(const float4*)&sX[k * 128 + n0v];
            float4 x1 = *(const float4*)&sX[k * 128 + n0v + 64];
            float xv[8] = {x0.x, x0.y, x0.z, x0.w, x1.x, x1.y, x1.z, x1.w};
            #pragma unroll
            for (int i = 0; i < 4; ++i) {
                float wv = W[(d0 + i) * 64 + k];
                #pragma unroll
                for (int j = 0; j < 8; ++j) acc[i][j] = fmaf(wv, xv[j], acc[i][j]);
            }
        }
        if (mat == 0) {
            // s: exact fp16 hi/lo split, [n][c] layout
            __half* outH = g_s_hi + (size_t)bb * N_SP * N_C;
            __half* outL = g_s_lo + (size_t)bb * N_SP * N_C;
            #pragma unroll
            for (int j = 0; j < 8; ++j) {
                int n = nbase + n0v + (j < 4 ? j : 60 + j);
                float v0 = acc[0][j] + sB[d0 + 0];
                float v1 = acc[1][j] + sB[d0 + 1];
                float v2 = acc[2][j] + sB[d0 + 2];
                float v3 = acc[3][j] + sB[d0 + 3];
                __half h0 = __float2half_rn(v0), h1 = __float2half_rn(v1);
                __half h2 = __float2half_rn(v2), h3 = __float2half_rn(v3);
                __half l0 = __float2half_rn(v0 - __half2float(h0));
                __half l1 = __float2half_rn(v1 - __half2float(h1));
                __half l2 = __float2half_rn(v2 - __half2float(h2));
                __half l3 = __float2half_rn(v3 - __half2float(h3));
                unsigned hi01 = (unsigned)__half_as_ushort(h0) | ((unsigned)__half_as_ushort(h1) << 16);
                unsigned hi23 = (unsigned)__half_as_ushort(h2) | ((unsigned)__half_as_ushort(h3) << 16);
                unsigned lo01 = (unsigned)__half_as_ushort(l0) | ((unsigned)__half_as_ushort(l1) << 16);
                unsigned lo23 = (unsigned)__half_as_ushort(l2) | ((unsigned)__half_as_ushort(l3) << 16);
                *(uint2*)&outH[(size_t)n * N_C + d0] = make_uint2(hi01, hi23);
                *(uint2*)&outL[(size_t)n * N_C + d0] = make_uint2(lo01, lo23);
            }
        } else if (mat == 1) {
            // f: single fp16, fused mma-fragment layout (128 B per row)
            #pragma unroll
            for (int j = 0; j < 8; ++j) {
                int n = nbase + n0v + (j < 4 ? j : 60 + j);
                float v0 = acc[0][j] + sB[64 + d0 + 0];
                float v1 = acc[1][j] + sB[64 + d0 + 1];
                float v2 = acc[2][j] + sB[64 + d0 + 2];
                float v3 = acc[3][j] + sB[64 + d0 + 3];
                __half h0 = __float2half_rn(v0), h1 = __float2half_rn(v1);
                __half h2 = __float2half_rn(v2), h3 = __float2half_rn(v3);
                unsigned p01 = (unsigned)__half_as_ushort(h0) | ((unsigned)__half_as_ushort(h1) << 16);
                unsigned p23 = (unsigned)__half_as_ushort(h2) | ((unsigned)__half_as_ushort(h3) << 16);
                uint8_t* fF = g_f_fused + (size_t)bb * N_SP * 128 + (size_t)n * 128;
                const int kb  = d0 >> 4;
                const int w0  = d0 & 15;
                const int tt0 = (w0 & 7) >> 1;       // pair0 -> t=tt0, pair1 -> t=tt0+1
                const int hi4 = (w0 & 8) ? 4 : 0;    // second k-octet slot
                *(unsigned*)(fF + (kb * 4 + tt0) * 8 + hi4)     = p01;
                *(unsigned*)(fF + (kb * 4 + tt0 + 1) * 8 + hi4) = p23;
            }
        } else {
            float* out = g_g + (size_t)bb * N_C * N_SP;
            #pragma unroll
            for (int i = 0; i < 4; ++i) {
                float bias = sB[128 + d0 + i];
                float4 o0 = make_float4(acc[i][0] + bias, acc[i][1] + bias, acc[i][2] + bias, acc[i][3] + bias);
                float4 o1 = make_float4(acc[i][4] + bias, acc[i][5] + bias, acc[i][6] + bias, acc[i][7] + bias);
                *(float4*)&out[(size_t)(d0 + i) * N_SP + nbase + n0v]      = o0;
                *(float4*)&out[(size_t)(d0 + i) * N_SP + nbase + n0v + 64] = o1;
            }
        }
    }
}

// ---------------------------------------------------------------------------
// sumx: per-(bb,c) spatial sums of the raw inputs.
// ---------------------------------------------------------------------------
__global__ __launch_bounds__(128) void sumx_kernel(const float* __restrict__ student,
                                                   const float* __restrict__ teacher)
{
    __shared__ float red[128];
    const int tid = threadIdx.x;
    const int bx = blockIdx.x;
    const int bb = bx >> 6, c = bx & 63;
    const float* x = (bb < 4 ? student : teacher) + ((size_t)(bb & 3) * N_C + c) * N_SP;
    float s = 0.f;
    for (int i = tid; i < N_SP; i += 128) s += x[i];
    red[tid] = s; __syncthreads();
    for (int off = 64; off > 0; off >>= 1) {
        if (tid < off) red[tid] += red[tid + off];
        __syncthreads();
    }
    if (tid == 0) g_sumx[bb * 64 + c] = red[0];
}

// ---------------------------------------------------------------------------
// attn helpers
// ---------------------------------------------------------------------------
__device__ __forceinline__ uint32_t smem_u32(const void* p) {
    uint32_t a;
    asm("{ .reg .u64 t; cvta.to.shared.u64 t, %1; cvt.u32.u64 %0, t; }" : "=r"(a) : "l"(p));
    return a;
}
__device__ __forceinline__ void cp_async16s(uint32_t dst, const void* src) {
    asm volatile("cp.async.cg.shared.global [%0], [%1], 16;" :: "r"(dst), "l"(src) : "memory");
}
__device__ __forceinline__ float ex2f(float x) {
    float r; asm("ex2.approx.ftz.f32 %0, %1;" : "=f"(r) : "f"(x)); return r;
}
#define MMAF16(c, a, b0, b1) \
    asm volatile("mma.sync.aligned.m16n8k16.row.col.f32.f16.f16.f32 " \
        "{%0,%1,%2,%3}, {%4,%5,%6,%7}, {%8,%9}, {%0,%1,%2,%3};" \
        : "+f"((c)[0]), "+f"((c)[1]), "+f"((c)[2]), "+f"((c)[3]) \
        : "r"((a)[0]), "r"((a)[1]), "r"((a)[2]), "r"((a)[3]), "r"(b0), "r"(b1))

// B tile smem: 128 rows x 160 B (128 data + 32 pad). LDS.64 lane map:
// bankpair = (g*160/8 + t) mod 16 = (4g + t) mod 16 -> distinct per 16-lane
// phase => conflict-free. Two buffers.
#define B_ROWSTR 160
#define B_BUF    (128 * B_ROWSTR)          // 20480 B

// ---------------------------------------------------------------------------
// attn: per warp 32 rows (2 m16 blocks; A hi/lo resident in regs).
// Per (nt,kb): 1 LDS.64 -> {b0,b1} feeds 4 mmas (2 row-blocks x 2 products).
// grid (16 rowtiles, 8 bb) = 128 CTAs, 256 thr, smem 40960B, 1 wave.
// ---------------------------------------------------------------------------
__global__ __launch_bounds__(256, 1) void attn_kernel()
{
    extern __shared__ char rawsm[];
    const uint32_t base = smem_u32(rawsm);
    const int tid = threadIdx.x;
    const int wid = tid >> 5, lane = tid & 31;
    const int g = lane >> 2, t = lane & 3;
    const int rowtile = blockIdx.x, bb = blockIdx.y;
    const int rbase = rowtile * 256;
    const __half* SH = g_s_hi + (size_t)bb * N_SP * N_C;
    const __half* SL = g_s_lo + (size_t)bb * N_SP * N_C;
    const uint8_t* FF = g_f_fused + (size_t)bb * N_SP * 128;

    // A fragments: 2 row-blocks x 4 kb x 4 regs, hi+lo (resident)
    uint32_t aH[2][4][4], aL[2][4][4];
    {
        const int r0 = rbase + 32 * wid + g;
        #pragma unroll
        for (int rb = 0; rb < 2; ++rb) {
            const int ra = r0 + 16 * rb, rbot = ra + 8;
            #pragma unroll
            for (int kb = 0; kb < 4; ++kb) {
                const int k0 = 16 * kb + 2 * t;
                aH[rb][kb][0] = *(const uint32_t*)&SH[(size_t)ra * N_C + k0];
                aH[rb][kb][1] = *(const uint32_t*)&SH[(size_t)rbot * N_C + k0];
                aH[rb][kb][2] = *(const uint32_t*)&SH[(size_t)ra * N_C + k0 + 8];
                aH[rb][kb][3] = *(const uint32_t*)&SH[(size_t)rbot * N_C + k0 + 8];
                aL[rb][kb][0] = *(const uint32_t*)&SL[(size_t)ra * N_C + k0];
                aL[rb][kb][1] = *(const uint32_t*)&SL[(size_t)rbot * N_C + k0];
                aL[rb][kb][2] = *(const uint32_t*)&SL[(size_t)ra * N_C + k0 + 8];
                aL[rb][kb][3] = *(const uint32_t*)&SL[(size_t)rbot * N_C + k0 + 8];
            }
        }
    }

    // prefetch B col-tiles 0 and 1 (128 rows x 128 B each)
    #pragma unroll
    for (int p = 0; p < 2; ++p) {
        #pragma unroll
        for (int i = 0; i < 4; ++i) {
            int ci = tid + i * 256;                 // 0..1023
            int row = ci >> 3, ch = ci & 7;
            cp_async16s(base + p * B_BUF + row * B_ROWSTR + ch * 16,
                        FF + (size_t)(p * 128 + row) * 128 + ch * 16);
        }
        asm volatile("cp.async.commit_group;" ::: "memory");
    }

    float e00 = 0.f, e01 = 0.f, e10 = 0.f, e11 = 0.f;

    for (int j = 0; j < 32; ++j) {
        asm volatile("cp.async.wait_group 1;" ::: "memory");
        __syncthreads();                            // tile j ready for all warps

        const char* buf = rawsm + (j & 1) * B_BUF;

        #pragma unroll 2
        for (int nt = 0; nt < 16; ++nt) {
            const char* rowp = buf + (nt * 8 + g) * B_ROWSTR + t * 8;
            uint2 bv[4];
            #pragma unroll
            for (int kb = 0; kb < 4; ++kb)
                bv[kb] = *(const uint2*)(rowp + kb * 32);

            float cA0[4] = {0.f,0.f,0.f,0.f}, cB0[4] = {0.f,0.f,0.f,0.f};
            float cA1[4] = {0.f,0.f,0.f,0.f}, cB1[4] = {0.f,0.f,0.f,0.f};
            #pragma unroll
            for (int kb = 0; kb < 4; ++kb) {
                MMAF16(cA0, aH[0][kb], bv[kb].x, bv[kb].y);
                MMAF16(cA1, aH[1][kb], bv[kb].x, bv[kb].y);
                MMAF16(cB0, aL[0][kb], bv[kb].x, bv[kb].y);
                MMAF16(cB1, aL[1][kb], bv[kb].x, bv[kb].y);
            }
            e00 += ex2f(cA0[0] + cB0[0]) + ex2f(cA0[1] + cB0[1]);
            e01 += ex2f(cA0[2] + cB0[2]) + ex2f(cA0[3] + cB0[3]);
            e10 += ex2f(cA1[0] + cB1[0]) + ex2f(cA1[1] + cB1[1]);
            e11 += ex2f(cA1[2] + cB1[2]) + ex2f(cA1[3] + cB1[3]);
        }

        __syncthreads();                            // all warps done with buffer j
        if (j + 2 < 32) {
            const int cb = (j + 2) * 128;
            #pragma unroll
            for (int i = 0; i < 4; ++i) {
                int ci = tid + i * 256;
                int row = ci >> 3, ch = ci & 7;
                cp_async16s(base + (j & 1) * B_BUF + row * B_ROWSTR + ch * 16,
                            FF + (size_t)(cb + row) * 128 + ch * 16);
            }
            asm volatile("cp.async.commit_group;" ::: "memory");
        }
    }

    // reduce over the 4 lanes (t) sharing each row
    #pragma unroll
    for (int off = 1; off < 4; off <<= 1) {
        e00 += __shfl_xor_sync(0xffffffffu, e00, off);
        e01 += __shfl_xor_sync(0xffffffffu, e01, off);
        e10 += __shfl_xor_sync(0xffffffffu, e10, off);
        e11 += __shfl_xor_sync(0xffffffffu, e11, off);
    }
    if (t == 0) {
        const int rb0 = bb * N_SP + rbase + 32 * wid + g;
        g_rowE[rb0]      = e00;
        g_rowE[rb0 + 8]  = e01;
        g_rowE[rb0 + 16] = e10;
        g_rowE[rb0 + 24] = e11;
    }
}

// ---------------------------------------------------------------------------
// qdot: one CTA per (bb,c): q = (sum_n g[c,n]*E_n) / (sum_n E_n). grid 512.
// ---------------------------------------------------------------------------
__global__ __launch_bounds__(128) void qdot_kernel()
{
    __shared__ float redP[4], redZ[4];
    const int tid = threadIdx.x;
    const int blk = blockIdx.x;
    const int bb = blk >> 6, c = blk & 63;
    const float4* gp = (const float4*)(g_g + (size_t)bb * N_C * N_SP + (size_t)c * N_SP);
    const float4* ep = (const float4*)(g_rowE + bb * N_SP);
    float p = 0.f, z = 0.f;
    #pragma unroll 2
    for (int i = tid; i < 1024; i += 128) {
        float4 a = gp[i], e = ep[i];
        p = fmaf(a.x, e.x, p); p = fmaf(a.y, e.y, p);
        p = fmaf(a.z, e.z, p); p = fmaf(a.w, e.w, p);
        z += (e.x + e.y) + (e.z + e.w);
    }
    #pragma unroll
    for (int off = 16; off > 0; off >>= 1) {
        p += __shfl_xor_sync(0xffffffffu, p, off);
        z += __shfl_xor_sync(0xffffffffu, z, off);
    }
    if ((tid & 31) == 0) { redP[tid >> 5] = p; redZ[tid >> 5] = z; }
    __syncthreads();
    if (tid == 0) {
        float P = redP[0] + redP[1] + redP[2] + redP[3];
        float Z = redZ[0] + redZ[1] + redZ[2] + redZ[3];
        g_q[bb * 64 + c] = P / Z;
    }
}

// ---------------------------------------------------------------------------
// loss: out[b,c] per branch, MSE-sum, scale.
// ---------------------------------------------------------------------------
__global__ __launch_bounds__(256) void loss_kernel(const float* __restrict__ fsg_w,
                                                   const float* __restrict__ fsg_b,
                                                   float* __restrict__ out, int out_size)
{
    __shared__ float red[256];
    const int tid = threadIdx.x;
    const int b = tid >> 6, d = tid & 63;
    float dot_s = 0.f, dot_t = 0.f;
    #pragma unroll 8
    for (int c = 0; c < 64; ++c) {
        float w = fsg_w[d * 64 + c];
        dot_s = fmaf(w, g_q[b * 64 + c], dot_s);
        dot_t = fmaf(w, g_q[(4 + b) * 64 + c], dot_t);
    }
    const float invN = 1.f / 4096.f;
    float out_s = g_sumx[b * 64 + d] * invN + dot_s * invN + fsg_b[d];
    float out_t = g_sumx[(4 + b) * 64 + d] * invN + dot_t * invN + fsg_b[d];
    float diff = out_s - out_t;
    red[tid] = diff * diff;
    __syncthreads();
    for (int off = 128; off > 0; off >>= 1) {
        if (tid < off) red[tid] += red[tid + off];
        __syncthreads();
    }
    const float nlB = 0.05f * 4e-4f * red[0];        // non_loss * B
    for (int i = tid; i < out_size; i += 256)
        out[i] = (i == 0) ? nlB : nlB * 0.25f;       // [non_loss*B, non_loss]
}

// ---------------------------------------------------------------------------
extern "C" void kernel_launch(void* const* d_in, const int* in_sizes, int n_in,
                              void* d_out, int out_size)
{
    (void)in_sizes; (void)n_in;
    const float* student = (const float*)d_in[0];
    const float* teacher = (const float*)d_in[1];
    const float* si_w  = (const float*)d_in[2];
    const float* si_b  = (const float*)d_in[3];
    const float* fi_w  = (const float*)d_in[4];
    const float* fi_b  = (const float*)d_in[5];
    const float* gi_w  = (const float*)d_in[6];
    const float* gi_b  = (const float*)d_in[7];
    const float* fsg_w = (const float*)d_in[8];
    const float* fsg_b = (const float*)d_in[9];

    cudaFuncSetAttribute(prep_kernel, cudaFuncAttributeMaxDynamicSharedMemorySize, 82688);
    cudaFuncSetAttribute(attn_kernel, cudaFuncAttributeMaxDynamicSharedMemorySize, 2 * B_BUF);

    prep_kernel<<<dim3(32, 8), 256, 82688>>>(student, teacher, si_w, si_b, fi_w, fi_b, gi_w, gi_b);
    sumx_kernel<<<512, 128>>>(student, teacher);
    attn_kernel<<<dim3(16, 8), 256, 2 * B_BUF>>>();
    qdot_kernel<<<512, 128>>>();
    loss_kernel<<<1, 256>>>(fsg_w, fsg_b, (float*)d_out, out_size);
}

// round 11
// speedup vs baseline: 4.7249x; 1.1673x over previous
#include <cuda_runtime.h>
#include <cuda_fp16.h>
#include <cstdint>

// NonLocalLoss: B=4, C=64, N=4096, two branches sharing weights.
// out[b,c] = mean_n x + (fsg_w @ q)/N + fsg_b ; q[c] = (sum_n g[c,n]*E_n)/Z
// E_n = sum_m 2^(F'_nm), F' = (log2e*s)^T f  (flat softmax, shift-invariant).
// F' via single-product fp16 mma.sync (sm_100-safe). A and B rounding each
// contribute ~2^-11 relative logit error; measured loss sensitivity (R10)
// puts the final rel_err at ~3e-6..1e-5 vs 1e-3 tolerance.

#define N_SP 4096
#define N_C  64
#define N_BB 8

// s in [n][c] fp16 (A operand, loaded to regs once per CTA)
__device__ __half g_s_h[(size_t)N_BB * N_SP * N_C];
// f fused fragment layout: per row n, 128 B; group (kb,t) at (kb*4+t)*8:
//   bytes 0-3: fp16 k=16kb+2t,2t+1 | bytes 4-7: fp16 k=16kb+8+2t,+1
__device__ uint8_t g_f_fused[(size_t)N_BB * N_SP * 128];
__device__ float g_g[(size_t)N_BB * N_C * N_SP];   // fp32 [C][N]
__device__ float g_rowE[N_BB * N_SP];
__device__ float g_q[N_BB * N_C];
__device__ float g_sumx[N_BB * N_C];

// ---------------------------------------------------------------------------
// prep: s,f,g = conv1x1(x). s scaled by log2e -> [n][c] fp16;
// f -> fused fp16 fragment layout; g -> fp32 [C][N].
// ---------------------------------------------------------------------------
__global__ __launch_bounds__(256) void prep_kernel(
    const float* __restrict__ student, const float* __restrict__ teacher,
    const float* __restrict__ si_w, const float* __restrict__ si_b,
    const float* __restrict__ fi_w, const float* __restrict__ fi_b,
    const float* __restrict__ gi_w, const float* __restrict__ gi_b)
{
    extern __shared__ float sm[];
    float* sX = sm;                    // [64][128]
    float* sW = sm + 8192;             // [3][64][64]
    float* sB = sm + 8192 + 12288;     // [3][64]
    const int tid = threadIdx.x;
    const int ntile = blockIdx.x, bb = blockIdx.y;
    const float* x = (bb < 4 ? student : teacher) + (size_t)(bb & 3) * N_C * N_SP;
    const int nbase = ntile * 128;
    const float LOG2E = 1.4426950408889634f;

    for (int i = tid; i < 8192; i += 256) {
        int c = i >> 7, j = i & 127;
        sX[i] = x[(size_t)c * N_SP + nbase + j];
    }
    for (int i = tid; i < 4096; i += 256) {
        sW[i]        = si_w[i] * LOG2E;
        sW[4096 + i] = fi_w[i];
        sW[8192 + i] = gi_w[i];
    }
    if (tid < 64) {
        sB[tid]       = si_b[tid] * LOG2E;
        sB[64 + tid]  = fi_b[tid];
        sB[128 + tid] = gi_b[tid];
    }
    __syncthreads();

    const int d0 = (tid >> 4) * 4, n0v = (tid & 15) * 4;
    #pragma unroll
    for (int mat = 0; mat < 3; ++mat) {
        const float* W = sW + mat * 4096;
        float acc[4][8];
        #pragma unroll
        for (int i = 0; i < 4; ++i)
            #pragma unroll
            for (int j = 0; j < 8; ++j) acc[i][j] = 0.f;

        #pragma unroll 4
        for (int k = 0; k < 64; ++k) {
            float4 x0 = *(const float4*)&sX[k * 128 + n0v];
            float4 x1 = *(const float4*)&sX[k * 128 + n0v + 64];
            float xv[8] = {x0.x, x0.y, x0.z, x0.w, x1.x, x1.y, x1.z, x1.w};
            #pragma unroll
            for (int i = 0; i < 4; ++i) {
                float wv = W[(d0 + i) * 64 + k];
                #pragma unroll
                for (int j = 0; j < 8; ++j) acc[i][j] = fmaf(wv, xv[j], acc[i][j]);
            }
        }
        if (mat == 0) {
            // s: fp16, [n][c] layout
            __half* outH = g_s_h + (size_t)bb * N_SP * N_C;
            #pragma unroll
            for (int j = 0; j < 8; ++j) {
                int n = nbase + n0v + (j < 4 ? j : 60 + j);
                __half h0 = __float2half_rn(acc[0][j] + sB[d0 + 0]);
                __half h1 = __float2half_rn(acc[1][j] + sB[d0 + 1]);
                __half h2 = __float2half_rn(acc[2][j] + sB[d0 + 2]);
                __half h3 = __float2half_rn(acc[3][j] + sB[d0 + 3]);
                unsigned hi01 = (unsigned)__half_as_ushort(h0) | ((unsigned)__half_as_ushort(h1) << 16);
                unsigned hi23 = (unsigned)__half_as_ushort(h2) | ((unsigned)__half_as_ushort(h3) << 16);
                *(uint2*)&outH[(size_t)n * N_C + d0] = make_uint2(hi01, hi23);
            }
        } else if (mat == 1) {
            // f: fp16, fused mma-fragment layout (128 B per row)
            #pragma unroll
            for (int j = 0; j < 8; ++j) {
                int n = nbase + n0v + (j < 4 ? j : 60 + j);
                __half h0 = __float2half_rn(acc[0][j] + sB[64 + d0 + 0]);
                __half h1 = __float2half_rn(acc[1][j] + sB[64 + d0 + 1]);
                __half h2 = __float2half_rn(acc[2][j] + sB[64 + d0 + 2]);
                __half h3 = __float2half_rn(acc[3][j] + sB[64 + d0 + 3]);
                unsigned p01 = (unsigned)__half_as_ushort(h0) | ((unsigned)__half_as_ushort(h1) << 16);
                unsigned p23 = (unsigned)__half_as_ushort(h2) | ((unsigned)__half_as_ushort(h3) << 16);
                uint8_t* fF = g_f_fused + (size_t)bb * N_SP * 128 + (size_t)n * 128;
                const int kb  = d0 >> 4;
                const int w0  = d0 & 15;
                const int tt0 = (w0 & 7) >> 1;       // pair0 -> t=tt0, pair1 -> t=tt0+1
                const int hi4 = (w0 & 8) ? 4 : 0;    // second k-octet slot
                *(unsigned*)(fF + (kb * 4 + tt0) * 8 + hi4)     = p01;
                *(unsigned*)(fF + (kb * 4 + tt0 + 1) * 8 + hi4) = p23;
            }
        } else {
            float* out = g_g + (size_t)bb * N_C * N_SP;
            #pragma unroll
            for (int i = 0; i < 4; ++i) {
                float bias = sB[128 + d0 + i];
                float4 o0 = make_float4(acc[i][0] + bias, acc[i][1] + bias, acc[i][2] + bias, acc[i][3] + bias);
                float4 o1 = make_float4(acc[i][4] + bias, acc[i][5] + bias, acc[i][6] + bias, acc[i][7] + bias);
                *(float4*)&out[(size_t)(d0 + i) * N_SP + nbase + n0v]      = o0;
                *(float4*)&out[(size_t)(d0 + i) * N_SP + nbase + n0v + 64] = o1;
            }
        }
    }
}

// ---------------------------------------------------------------------------
// sumx: per-(bb,c) spatial sums of the raw inputs.
// ---------------------------------------------------------------------------
__global__ __launch_bounds__(128) void sumx_kernel(const float* __restrict__ student,
                                                   const float* __restrict__ teacher)
{
    __shared__ float red[128];
    const int tid = threadIdx.x;
    const int bx = blockIdx.x;
    const int bb = bx >> 6, c = bx & 63;
    const float* x = (bb < 4 ? student : teacher) + ((size_t)(bb & 3) * N_C + c) * N_SP;
    float s = 0.f;
    for (int i = tid; i < N_SP; i += 128) s += x[i];
    red[tid] = s; __syncthreads();
    for (int off = 64; off > 0; off >>= 1) {
        if (tid < off) red[tid] += red[tid + off];
        __syncthreads();
    }
    if (tid == 0) g_sumx[bb * 64 + c] = red[0];
}

// ---------------------------------------------------------------------------
// attn helpers
// ---------------------------------------------------------------------------
__device__ __forceinline__ uint32_t smem_u32(const void* p) {
    uint32_t a;
    asm("{ .reg .u64 t; cvta.to.shared.u64 t, %1; cvt.u32.u64 %0, t; }" : "=r"(a) : "l"(p));
    return a;
}
__device__ __forceinline__ void cp_async16s(uint32_t dst, const void* src) {
    asm volatile("cp.async.cg.shared.global [%0], [%1], 16;" :: "r"(dst), "l"(src) : "memory");
}
__device__ __forceinline__ float ex2f(float x) {
    float r; asm("ex2.approx.ftz.f32 %0, %1;" : "=f"(r) : "f"(x)); return r;
}
#define MMAF16(c, a, b0, b1) \
    asm volatile("mma.sync.aligned.m16n8k16.row.col.f32.f16.f16.f32 " \
        "{%0,%1,%2,%3}, {%4,%5,%6,%7}, {%8,%9}, {%0,%1,%2,%3};" \
        : "+f"((c)[0]), "+f"((c)[1]), "+f"((c)[2]), "+f"((c)[3]) \
        : "r"((a)[0]), "r"((a)[1]), "r"((a)[2]), "r"((a)[3]), "r"(b0), "r"(b1))

// B tile smem: 128 rows x 160 B (128 data + 32 pad). LDS.64 lane map:
// bankpair = (4g + t) mod 16 -> distinct per 16-lane phase => conflict-free.
#define B_ROWSTR 160
#define B_BUF    (128 * B_ROWSTR)          // 20480 B

// ---------------------------------------------------------------------------
// attn: per warp 32 rows (2 m16 blocks; A fp16 resident in regs).
// Per (nt,kb): 1 LDS.64 -> {b0,b1} feeds 2 mmas (2 row-blocks, 1 product).
// grid (16 rowtiles, 8 bb) = 128 CTAs, 256 thr, smem 40960B, 1 wave.
// ---------------------------------------------------------------------------
__global__ __launch_bounds__(256, 1) void attn_kernel()
{
    extern __shared__ char rawsm[];
    const uint32_t base = smem_u32(rawsm);
    const int tid = threadIdx.x;
    const int wid = tid >> 5, lane = tid & 31;
    const int g = lane >> 2, t = lane & 3;
    const int rowtile = blockIdx.x, bb = blockIdx.y;
    const int rbase = rowtile * 256;
    const __half* SH = g_s_h + (size_t)bb * N_SP * N_C;
    const uint8_t* FF = g_f_fused + (size_t)bb * N_SP * 128;

    // A fragments: 2 row-blocks x 4 kb x 4 regs (resident)
    uint32_t aH[2][4][4];
    {
        const int r0 = rbase + 32 * wid + g;
        #pragma unroll
        for (int rb = 0; rb < 2; ++rb) {
            const int ra = r0 + 16 * rb, rbot = ra + 8;
            #pragma unroll
            for (int kb = 0; kb < 4; ++kb) {
                const int k0 = 16 * kb + 2 * t;
                aH[rb][kb][0] = *(const uint32_t*)&SH[(size_t)ra * N_C + k0];
                aH[rb][kb][1] = *(const uint32_t*)&SH[(size_t)rbot * N_C + k0];
                aH[rb][kb][2] = *(const uint32_t*)&SH[(size_t)ra * N_C + k0 + 8];
                aH[rb][kb][3] = *(const uint32_t*)&SH[(size_t)rbot * N_C + k0 + 8];
            }
        }
    }

    // prefetch B col-tiles 0 and 1 (128 rows x 128 B each)
    #pragma unroll
    for (int p = 0; p < 2; ++p) {
        #pragma unroll
        for (int i = 0; i < 4; ++i) {
            int ci = tid + i * 256;                 // 0..1023
            int row = ci >> 3, ch = ci & 7;
            cp_async16s(base + p * B_BUF + row * B_ROWSTR + ch * 16,
                        FF + (size_t)(p * 128 + row) * 128 + ch * 16);
        }
        asm volatile("cp.async.commit_group;" ::: "memory");
    }

    float e00 = 0.f, e01 = 0.f, e10 = 0.f, e11 = 0.f;

    for (int j = 0; j < 32; ++j) {
        asm volatile("cp.async.wait_group 1;" ::: "memory");
        __syncthreads();                            // tile j ready for all warps

        const char* buf = rawsm + (j & 1) * B_BUF;

        #pragma unroll 2
        for (int nt = 0; nt < 16; ++nt) {
            const char* rowp = buf + (nt * 8 + g) * B_ROWSTR + t * 8;
            uint2 bv[4];
            #pragma unroll
            for (int kb = 0; kb < 4; ++kb)
                bv[kb] = *(const uint2*)(rowp + kb * 32);

            float cA0[4] = {0.f,0.f,0.f,0.f};
            float cA1[4] = {0.f,0.f,0.f,0.f};
            #pragma unroll
            for (int kb = 0; kb < 4; ++kb) {
                MMAF16(cA0, aH[0][kb], bv[kb].x, bv[kb].y);
                MMAF16(cA1, aH[1][kb], bv[kb].x, bv[kb].y);
            }
            e00 += ex2f(cA0[0]) + ex2f(cA0[1]);
            e01 += ex2f(cA0[2]) + ex2f(cA0[3]);
            e10 += ex2f(cA1[0]) + ex2f(cA1[1]);
            e11 += ex2f(cA1[2]) + ex2f(cA1[3]);
        }

        __syncthreads();                            // all warps done with buffer j
        if (j + 2 < 32) {
            const int cb = (j + 2) * 128;
            #pragma unroll
            for (int i = 0; i < 4; ++i) {
                int ci = tid + i * 256;
                int row = ci >> 3, ch = ci & 7;
                cp_async16s(base + (j & 1) * B_BUF + row * B_ROWSTR + ch * 16,
                            FF + (size_t)(cb + row) * 128 + ch * 16);
            }
            asm volatile("cp.async.commit_group;" ::: "memory");
        }
    }

    // reduce over the 4 lanes (t) sharing each row
    #pragma unroll
    for (int off = 1; off < 4; off <<= 1) {
        e00 += __shfl_xor_sync(0xffffffffu, e00, off);
        e01 += __shfl_xor_sync(0xffffffffu, e01, off);
        e10 += __shfl_xor_sync(0xffffffffu, e10, off);
        e11 += __shfl_xor_sync(0xffffffffu, e11, off);
    }
    if (t == 0) {
        const int rb0 = bb * N_SP + rbase + 32 * wid + g;
        g_rowE[rb0]      = e00;
        g_rowE[rb0 + 8]  = e01;
        g_rowE[rb0 + 16] = e10;
        g_rowE[rb0 + 24] = e11;
    }
}

// ---------------------------------------------------------------------------
// qdot: one CTA per (bb,c): q = (sum_n g[c,n]*E_n) / (sum_n E_n). grid 512.
// ---------------------------------------------------------------------------
__global__ __launch_bounds__(128) void qdot_kernel()
{
    __shared__ float redP[4], redZ[4];
    const int tid = threadIdx.x;
    const int blk = blockIdx.x;
    const int bb = blk >> 6, c = blk & 63;
    const float4* gp = (const float4*)(g_g + (size_t)bb * N_C * N_SP + (size_t)c * N_SP);
    const float4* ep = (const float4*)(g_rowE + bb * N_SP);
    float p = 0.f, z = 0.f;
    #pragma unroll 2
    for (int i = tid; i < 1024; i += 128) {
        float4 a = gp[i], e = ep[i];
        p = fmaf(a.x, e.x, p); p = fmaf(a.y, e.y, p);
        p = fmaf(a.z, e.z, p); p = fmaf(a.w, e.w, p);
        z += (e.x + e.y) + (e.z + e.w);
    }
    #pragma unroll
    for (int off = 16; off > 0; off >>= 1) {
        p += __shfl_xor_sync(0xffffffffu, p, off);
        z += __shfl_xor_sync(0xffffffffu, z, off);
    }
    if ((tid & 31) == 0) { redP[tid >> 5] = p; redZ[tid >> 5] = z; }
    __syncthreads();
    if (tid == 0) {
        float P = redP[0] + redP[1] + redP[2] + redP[3];
        float Z = redZ[0] + redZ[1] + redZ[2] + redZ[3];
        g_q[bb * 64 + c] = P / Z;
    }
}

// ---------------------------------------------------------------------------
// loss: out[b,c] per branch, MSE-sum, scale.
// ---------------------------------------------------------------------------
__global__ __launch_bounds__(256) void loss_kernel(const float* __restrict__ fsg_w,
                                                   const float* __restrict__ fsg_b,
                                                   float* __restrict__ out, int out_size)
{
    __shared__ float red[256];
    const int tid = threadIdx.x;
    const int b = tid >> 6, d = tid & 63;
    float dot_s = 0.f, dot_t = 0.f;
    #pragma unroll 8
    for (int c = 0; c < 64; ++c) {
        float w = fsg_w[d * 64 + c];
        dot_s = fmaf(w, g_q[b * 64 + c], dot_s);
        dot_t = fmaf(w, g_q[(4 + b) * 64 + c], dot_t);
    }
    const float invN = 1.f / 4096.f;
    float out_s = g_sumx[b * 64 + d] * invN + dot_s * invN + fsg_b[d];
    float out_t = g_sumx[(4 + b) * 64 + d] * invN + dot_t * invN + fsg_b[d];
    float diff = out_s - out_t;
    red[tid] = diff * diff;
    __syncthreads();
    for (int off = 128; off > 0; off >>= 1) {
        if (tid < off) red[tid] += red[tid + off];
        __syncthreads();
    }
    const float nlB = 0.05f * 4e-4f * red[0];        // non_loss * B
    for (int i = tid; i < out_size; i += 256)
        out[i] = (i == 0) ? nlB : nlB * 0.25f;       // [non_loss*B, non_loss]
}

// ---------------------------------------------------------------------------
extern "C" void kernel_launch(void* const* d_in, const int* in_sizes, int n_in,
                              void* d_out, int out_size)
{
    (void)in_sizes; (void)n_in;
    const float* student = (const float*)d_in[0];
    const float* teacher = (const float*)d_in[1];
    const float* si_w  = (const float*)d_in[2];
    const float* si_b  = (const float*)d_in[3];
    const float* fi_w  = (const float*)d_in[4];
    const float* fi_b  = (const float*)d_in[5];
    const float* gi_w  = (const float*)d_in[6];
    const float* gi_b  = (const float*)d_in[7];
    const float* fsg_w = (const float*)d_in[8];
    const float* fsg_b = (const float*)d_in[9];

    cudaFuncSetAttribute(prep_kernel, cudaFuncAttributeMaxDynamicSharedMemorySize, 82688);
    cudaFuncSetAttribute(attn_kernel, cudaFuncAttributeMaxDynamicSharedMemorySize, 2 * B_BUF);

    prep_kernel<<<dim3(32, 8), 256, 82688>>>(student, teacher, si_w, si_b, fi_w, fi_b, gi_w, gi_b);
    sumx_kernel<<<512, 128>>>(student, teacher);
    attn_kernel<<<dim3(16, 8), 256, 2 * B_BUF>>>();
    qdot_kernel<<<512, 128>>>();
    loss_kernel<<<1, 256>>>(fsg_w, fsg_b, (float*)d_out, out_size);
}